// round 11
// baseline (speedup 1.0000x reference)
#include <cuda_runtime.h>
#include <cuda_bf16.h>
#include <mma.h>
#include <math.h>

using namespace nvcuda;

#define B_   64
#define S_   577
#define D_   768
#define H_   12
#define DH_  64
#define FF_  3072
#define NT_  (B_ * S_)          // 36928 tokens

// ---------------- scratch ----------------
__device__ float g_h[(size_t)NT_ * D_];
__device__ float g_qkv[(size_t)NT_ * 3 * D_];
__device__ float g_attn[(size_t)NT_ * D_];
__device__ float g_ff[(size_t)NT_ * FF_];
__device__ float g_wqkv[(size_t)D_ * 3 * D_];
__device__ float g_bqkv[3 * D_];
__device__ float g_wor[(size_t)D_ * D_];
__device__ float g_w1r[(size_t)D_ * FF_];
__device__ float g_w2r[(size_t)FF_ * D_];

// ---------------- helpers ----------------
__device__ __forceinline__ float tf32r(float x) { return wmma::__float_to_tf32(x); }

__device__ __forceinline__ float gelu_tanh(float x) {
    const float c = 0.7978845608028654f;
    float x3 = x * x * x;
    return 0.5f * x * (1.0f + tanhf(c * (x + 0.044715f * x3)));
}

__device__ __forceinline__ void cp_async16(float* s, const float* g, bool pred) {
    unsigned saddr = (unsigned)__cvta_generic_to_shared(s);
    int sz = pred ? 16 : 0;
    asm volatile("cp.async.cg.shared.global [%0], [%1], 16, %2;\n"
                 :: "r"(saddr), "l"(g), "r"(sz));
}
__device__ __forceinline__ void cp_commit() { asm volatile("cp.async.commit_group;\n"); }
template <int N>
__device__ __forceinline__ void cp_wait() { asm volatile("cp.async.wait_group %0;\n" :: "n"(N)); }

// ---------------- round-copy (RN tf32) ----------------
__global__ void round_copy_kernel(const float* __restrict__ in, float* __restrict__ out, int n) {
    int i = blockIdx.x * blockDim.x + threadIdx.x;
    if (i < n) out[i] = tf32r(in[i]);
}

// ---------------- pack per-head QKV weights into fused [D, 2304] (rounded) ----------------
__global__ void pack_qkv_kernel(const float* __restrict__ Wq, const float* __restrict__ Wk,
                                const float* __restrict__ Wv, const float* __restrict__ bq,
                                const float* __restrict__ bk, const float* __restrict__ bv) {
    size_t idx = (size_t)blockIdx.x * blockDim.x + threadIdx.x;
    size_t total = (size_t)D_ * 3 * D_;
    if (idx >= total) return;
    int d  = (int)(idx / (3 * D_));
    int j  = (int)(idx % (3 * D_));
    int sel = j / D_;
    int jj  = j % D_;
    int h = jj / DH_;
    int e = jj % DH_;
    const float* W = (sel == 0) ? Wq : (sel == 1) ? Wk : Wv;
    g_wqkv[idx] = tf32r(W[((size_t)h * D_ + d) * DH_ + e]);
    if (d == 0) {
        const float* bb = (sel == 0) ? bq : (sel == 1) ? bk : bv;
        g_bqkv[j] = bb[jj];
    }
}

// ---------------- LayerNorm (tf32-rounded output) ----------------
__global__ __launch_bounds__(256) void ln_kernel(const float* __restrict__ x,
                                                 const float* __restrict__ g,
                                                 const float* __restrict__ bet,
                                                 float* __restrict__ out) {
    int t = blockIdx.x;
    const float* xr = x + (size_t)t * D_;
    float* orow = out + (size_t)t * D_;
    int tid = threadIdx.x;
    float v0 = xr[tid], v1 = xr[tid + 256], v2 = xr[tid + 512];
    float s  = v0 + v1 + v2;
    float ss = v0 * v0 + v1 * v1 + v2 * v2;
    #pragma unroll
    for (int o = 16; o > 0; o >>= 1) {
        s  += __shfl_xor_sync(0xffffffffu, s, o);
        ss += __shfl_xor_sync(0xffffffffu, ss, o);
    }
    __shared__ float sh[16];
    __shared__ float mb[2];
    int w = tid >> 5, lane = tid & 31;
    if (lane == 0) { sh[w] = s; sh[w + 8] = ss; }
    __syncthreads();
    if (tid == 0) {
        float S1 = 0.f, S2 = 0.f;
        #pragma unroll
        for (int i = 0; i < 8; i++) { S1 += sh[i]; S2 += sh[i + 8]; }
        float mean = S1 * (1.0f / D_);
        float var  = S2 * (1.0f / D_) - mean * mean;
        mb[0] = mean;
        mb[1] = rsqrtf(var + 1e-6f);
    }
    __syncthreads();
    float mean = mb[0], rstd = mb[1];
    orow[tid]       = tf32r((v0 - mean) * rstd * g[tid]       + bet[tid]);
    orow[tid + 256] = tf32r((v1 - mean) * rstd * g[tid + 256] + bet[tid + 256]);
    orow[tid + 512] = tf32r((v2 - mean) * rstd * g[tid + 512] + bet[tid + 512]);
}

// ---------------- tf32 SGEMM: 128x128x32, 128 thr (4 warps, 64x64), 2-stage, 3 CTA/SM ----------------
#define GBM 128
#define GBN 128
#define GBK 32
#define A_LD 36
#define B_LD 132
#define ASZ (GBM * A_LD)
#define BSZ (GBK * B_LD)
#define GEMM_SMEM_FLOATS (2 * ASZ + 2 * BSZ)
#define GEMM_SMEM_BYTES  (GEMM_SMEM_FLOATS * 4)   // 70,656 B

template <int EPI, bool RND>
__global__ __launch_bounds__(128, 3) void sgemm_tc(const float* __restrict__ A,
                                                   const float* __restrict__ Bw,
                                                   const float* __restrict__ bias,
                                                   const float* __restrict__ res,
                                                   float* __restrict__ C,
                                                   int M, int N, int K) {
    extern __shared__ float dsm[];
    float* As = dsm;
    float* Bs = dsm + 2 * ASZ;

    int tid = threadIdx.x;
    int wid = tid >> 5, lane = tid & 31;
    int warp_m = wid & 1;        // 2 x 64 rows
    int warp_n = wid >> 1;       // 2 x 64 cols
    int blockM = blockIdx.y * GBM;
    int blockN = blockIdx.x * GBN;

    int aRow = tid >> 2;          // 0..31 (+32/pass)
    int aCol = (tid & 3) * 8;
    int bRow = tid >> 5;          // 0..3 (+4/pass)
    int bCol = (tid & 31) * 4;

    int nk = K / GBK;

    auto issue_tile = [&](int t, int buf) {
        int k0 = t * GBK;
        float* Ad = As + buf * ASZ;
        float* Bd = Bs + buf * BSZ;
        #pragma unroll
        for (int p = 0; p < 4; p++) {
            int r = aRow + p * 32;
            bool ok = (blockM + r) < M;
            const float* gp = A + (size_t)(ok ? (blockM + r) : 0) * K + k0 + aCol;
            cp_async16(Ad + r * A_LD + aCol,     gp,     ok);
            cp_async16(Ad + r * A_LD + aCol + 4, gp + 4, ok);
        }
        #pragma unroll
        for (int p = 0; p < 8; p++) {
            int r = bRow + p * 4;
            const float* gp = Bw + (size_t)(k0 + r) * N + blockN + bCol;
            cp_async16(Bd + r * B_LD + bCol, gp, true);
        }
    };

    wmma::fragment<wmma::accumulator, 16, 16, 8, float> acc[4][4];
    #pragma unroll
    for (int i = 0; i < 4; i++)
        #pragma unroll
        for (int j = 0; j < 4; j++) wmma::fill_fragment(acc[i][j], 0.0f);

    issue_tile(0, 0); cp_commit();

    for (int t = 0; t < nk; t++) {
        if (t + 1 < nk) {
            issue_tile(t + 1, (t + 1) & 1);
            cp_commit();
            cp_wait<1>();
        } else {
            cp_wait<0>();
        }
        __syncthreads();

        int buf = t & 1;
        float* Ab = As + buf * ASZ;
        float* Bb = Bs + buf * BSZ;
        #pragma unroll
        for (int ks = 0; ks < 4; ks++) {
            wmma::fragment<wmma::matrix_a, 16, 16, 8, wmma::precision::tf32, wmma::row_major> af[4];
            wmma::fragment<wmma::matrix_b, 16, 16, 8, wmma::precision::tf32, wmma::row_major> bf[4];
            #pragma unroll
            for (int i = 0; i < 4; i++)
                wmma::load_matrix_sync(af[i], Ab + (warp_m * 64 + i * 16) * A_LD + ks * 8, A_LD);
            #pragma unroll
            for (int j = 0; j < 4; j++)
                wmma::load_matrix_sync(bf[j], Bb + (ks * 8) * B_LD + warp_n * 64 + j * 16, B_LD);
            #pragma unroll
            for (int i = 0; i < 4; i++)
                #pragma unroll
                for (int j = 0; j < 4; j++)
                    wmma::mma_sync(acc[i][j], af[i], bf[j], acc[i][j]);
        }
        __syncthreads();   // buffer free before t+2 overwrites it
    }

    float* st = dsm + wid * 320;
    int r  = lane >> 1;
    int c0 = (lane & 1) * 8;
    #pragma unroll
    for (int i = 0; i < 4; i++) {
        #pragma unroll
        for (int j = 0; j < 4; j++) {
            wmma::store_matrix_sync(st, acc[i][j], 20, wmma::mem_row_major);
            __syncwarp();
            int grow = blockM + warp_m * 64 + i * 16 + r;
            int gcol = blockN + warp_n * 64 + j * 16 + c0;
            if (grow < M) {
                #pragma unroll
                for (int cc = 0; cc < 8; cc++) {
                    float v = st[r * 20 + c0 + cc] + bias[gcol + cc];
                    if (EPI == 1) v = gelu_tanh(v);
                    else if (EPI == 2) v += res[(size_t)grow * N + gcol + cc];
                    if (RND) v = tf32r(v);
                    C[(size_t)grow * N + gcol + cc] = v;
                }
            }
            __syncwarp();
        }
    }
}

// ---------------- flash attention: streaming softmax, 256 thr, 2 CTA/SM (R9, unchanged) ----------------
#define SKT 10
#define TLD 68
#define T_F (64 * TLD)
#define AF_SMEM_FLOATS (5 * T_F + 64)
#define AF_SMEM_BYTES  (AF_SMEM_FLOATS * 4)   // 87,296 B

__global__ __launch_bounds__(256, 2) void attn_flash(const float* __restrict__ qkv,
                                                     float* __restrict__ attn) {
    extern __shared__ float sm[];
    float* qs   = sm;
    float* ks   = sm + T_F;
    float* vs   = sm + 2 * T_F;
    float* ps   = sm + 3 * T_F;
    float* os   = sm + 4 * T_F;
    float* crow = sm + 5 * T_F;

    int bh = blockIdx.y;
    int b = bh / H_, h = bh % H_;
    int qt = blockIdx.x;
    int tid = threadIdx.x;
    int wid = tid >> 5, lane = tid & 31;
    int warp_m  = wid & 3;
    int warp_nh = wid >> 2;

    int lr  = tid >> 2;
    int lc0 = (tid & 3) * 16;

    {
        int gq = qt * 64 + lr;
        bool qok = gq < S_;
        const float* qp = &qkv[((size_t)(b * S_ + (qok ? gq : 0))) * (3 * D_) + h * DH_];
        #pragma unroll
        for (int i = 0; i < 4; i++) {
            float4 v = qok ? *(const float4*)&qp[lc0 + i * 4] : make_float4(0.f, 0.f, 0.f, 0.f);
            *(float4*)&qs[lr * TLD + lc0 + i * 4] = v;
        }
        for (int i = tid; i < T_F; i += 256) os[i] = 0.f;
    }

    float mrow[8], lrow[8];
    #pragma unroll
    for (int rr = 0; rr < 8; rr++) { mrow[rr] = -1e30f; lrow[rr] = 0.f; }

    for (int kt = 0; kt < SKT; kt++) {
        __syncthreads();
        {
            int gk = kt * 64 + lr;
            bool kok = gk < S_;
            const float* kp = &qkv[((size_t)(b * S_ + (kok ? gk : 0))) * (3 * D_) + D_ + h * DH_];
            const float* vp = &qkv[((size_t)(b * S_ + (kok ? gk : 0))) * (3 * D_) + 2 * D_ + h * DH_];
            #pragma unroll
            for (int i = 0; i < 4; i++) {
                float4 kv = kok ? *(const float4*)&kp[lc0 + i * 4] : make_float4(0.f, 0.f, 0.f, 0.f);
                float4 vv = kok ? *(const float4*)&vp[lc0 + i * 4] : make_float4(0.f, 0.f, 0.f, 0.f);
                *(float4*)&ks[lr * TLD + lc0 + i * 4] = kv;
                *(float4*)&vs[lr * TLD + lc0 + i * 4] = vv;
            }
        }
        __syncthreads();

        {
            wmma::fragment<wmma::accumulator, 16, 16, 8, float> sacc[2];
            #pragma unroll
            for (int j = 0; j < 2; j++) wmma::fill_fragment(sacc[j], 0.0f);
            #pragma unroll
            for (int kk = 0; kk < 8; kk++) {
                wmma::fragment<wmma::matrix_a, 16, 16, 8, wmma::precision::tf32, wmma::row_major> af;
                wmma::load_matrix_sync(af, qs + (warp_m * 16) * TLD + kk * 8, TLD);
                #pragma unroll
                for (int j = 0; j < 2; j++) {
                    wmma::fragment<wmma::matrix_b, 16, 16, 8, wmma::precision::tf32, wmma::col_major> bf;
                    wmma::load_matrix_sync(bf, ks + (warp_nh * 32 + j * 16) * TLD + kk * 8, TLD);
                    wmma::mma_sync(sacc[j], af, bf, sacc[j]);
                }
            }
            #pragma unroll
            for (int j = 0; j < 2; j++) {
                #pragma unroll
                for (int e = 0; e < sacc[j].num_elements; e++) sacc[j].x[e] *= 0.125f;
                wmma::store_matrix_sync(ps + (warp_m * 16) * TLD + warp_nh * 32 + j * 16,
                                        sacc[j], TLD, wmma::mem_row_major);
            }
        }
        __syncthreads();

        #pragma unroll
        for (int rr = 0; rr < 8; rr++) {
            int r = wid * 8 + rr;
            float* row = ps + r * TLD;
            int gc0 = kt * 64 + lane;
            int gc1 = gc0 + 32;
            float a0 = (gc0 < S_) ? row[lane]      : -1e30f;
            float a1 = (gc1 < S_) ? row[lane + 32] : -1e30f;
            float tmax = fmaxf(a0, a1);
            #pragma unroll
            for (int o = 16; o > 0; o >>= 1) tmax = fmaxf(tmax, __shfl_xor_sync(0xffffffffu, tmax, o));
            float m_new = fmaxf(mrow[rr], tmax);
            float corr = __expf(mrow[rr] - m_new);
            float p0 = (gc0 < S_) ? __expf(a0 - m_new) : 0.f;
            float p1 = (gc1 < S_) ? __expf(a1 - m_new) : 0.f;
            float tsum = p0 + p1;
            #pragma unroll
            for (int o = 16; o > 0; o >>= 1) tsum += __shfl_xor_sync(0xffffffffu, tsum, o);
            lrow[rr] = lrow[rr] * corr + tsum;
            mrow[rr] = m_new;
            row[lane]      = tf32r(p0);
            row[lane + 32] = tf32r(p1);
            if (lane == 0) crow[r] = corr;
        }
        __syncthreads();

        {
            float c = crow[lr];
            #pragma unroll
            for (int i = 0; i < 16; i++) os[lr * TLD + lc0 + i] *= c;
        }
        __syncthreads();

        {
            wmma::fragment<wmma::accumulator, 16, 16, 8, float> oacc[2];
            #pragma unroll
            for (int j = 0; j < 2; j++)
                wmma::load_matrix_sync(oacc[j], os + (warp_m * 16) * TLD + warp_nh * 32 + j * 16,
                                       TLD, wmma::mem_row_major);
            #pragma unroll
            for (int kk = 0; kk < 8; kk++) {
                wmma::fragment<wmma::matrix_a, 16, 16, 8, wmma::precision::tf32, wmma::row_major> af;
                wmma::load_matrix_sync(af, ps + (warp_m * 16) * TLD + kk * 8, TLD);
                #pragma unroll
                for (int j = 0; j < 2; j++) {
                    wmma::fragment<wmma::matrix_b, 16, 16, 8, wmma::precision::tf32, wmma::row_major> bf;
                    wmma::load_matrix_sync(bf, vs + (kk * 8) * TLD + warp_nh * 32 + j * 16, TLD);
                    wmma::mma_sync(oacc[j], af, bf, oacc[j]);
                }
            }
            #pragma unroll
            for (int j = 0; j < 2; j++)
                wmma::store_matrix_sync(os + (warp_m * 16) * TLD + warp_nh * 32 + j * 16,
                                        oacc[j], TLD, wmma::mem_row_major);
        }
    }
    __syncthreads();

    #pragma unroll
    for (int rr = 0; rr < 8; rr++) {
        int rloc = wid * 8 + rr;
        int gi = qt * 64 + rloc;
        if (gi >= S_) continue;
        float linv = 1.0f / lrow[rr];
        float* orow = &attn[((size_t)(b * S_ + gi)) * D_ + h * DH_];
        int c = lane * 2;
        orow[c]     = tf32r(os[rloc * TLD + c] * linv);
        orow[c + 1] = tf32r(os[rloc * TLD + c + 1] * linv);
    }
}

// ---------------- launch ----------------
extern "C" void kernel_launch(void* const* d_in, const int* in_sizes, int n_in,
                              void* d_out, int out_size) {
    const float* x     = (const float*)d_in[0];
    const float* ln1_g = (const float*)d_in[1];
    const float* ln1_b = (const float*)d_in[2];
    const float* Wq    = (const float*)d_in[3];
    const float* bq    = (const float*)d_in[4];
    const float* Wk    = (const float*)d_in[5];
    const float* bk    = (const float*)d_in[6];
    const float* Wv    = (const float*)d_in[7];
    const float* bv    = (const float*)d_in[8];
    const float* Wo    = (const float*)d_in[9];
    const float* bo    = (const float*)d_in[10];
    const float* ln2_g = (const float*)d_in[11];
    const float* ln2_b = (const float*)d_in[12];
    const float* W1    = (const float*)d_in[13];
    const float* b1    = (const float*)d_in[14];
    const float* W2    = (const float*)d_in[15];
    const float* b2    = (const float*)d_in[16];
    float* out = (float*)d_out;

    float* h_p;    cudaGetSymbolAddress((void**)&h_p, g_h);
    float* qkv_p;  cudaGetSymbolAddress((void**)&qkv_p, g_qkv);
    float* attn_p; cudaGetSymbolAddress((void**)&attn_p, g_attn);
    float* ff_p;   cudaGetSymbolAddress((void**)&ff_p, g_ff);
    float* wqkv_p; cudaGetSymbolAddress((void**)&wqkv_p, g_wqkv);
    float* bqkv_p; cudaGetSymbolAddress((void**)&bqkv_p, g_bqkv);
    float* wor_p;  cudaGetSymbolAddress((void**)&wor_p, g_wor);
    float* w1r_p;  cudaGetSymbolAddress((void**)&w1r_p, g_w1r);
    float* w2r_p;  cudaGetSymbolAddress((void**)&w2r_p, g_w2r);

    cudaFuncSetAttribute((const void*)sgemm_tc<0, true>,  cudaFuncAttributeMaxDynamicSharedMemorySize, GEMM_SMEM_BYTES);
    cudaFuncSetAttribute((const void*)sgemm_tc<1, true>,  cudaFuncAttributeMaxDynamicSharedMemorySize, GEMM_SMEM_BYTES);
    cudaFuncSetAttribute((const void*)sgemm_tc<2, false>, cudaFuncAttributeMaxDynamicSharedMemorySize, GEMM_SMEM_BYTES);
    cudaFuncSetAttribute((const void*)attn_flash, cudaFuncAttributeMaxDynamicSharedMemorySize, AF_SMEM_BYTES);

    // 0. round weight copies (RN tf32)
    {
        int n1 = D_ * D_;
        round_copy_kernel<<<(n1 + 255) / 256, 256>>>(Wo, wor_p, n1);
        int n2 = D_ * FF_;
        round_copy_kernel<<<(n2 + 255) / 256, 256>>>(W1, w1r_p, n2);
        round_copy_kernel<<<(n2 + 255) / 256, 256>>>(W2, w2r_p, n2);
    }
    // 1. pack fused QKV weights (rounded)
    {
        size_t total = (size_t)D_ * 3 * D_;
        pack_qkv_kernel<<<(int)((total + 255) / 256), 256>>>(Wq, Wk, Wv, bq, bk, bv);
    }
    // 2. LN1 (rounded output)
    ln_kernel<<<NT_, 256>>>(x, ln1_g, ln1_b, h_p);
    // 3. fused QKV GEMM (rounded output)
    {
        dim3 grid(3 * D_ / GBN, (NT_ + GBM - 1) / GBM);
        sgemm_tc<0, true><<<grid, 128, GEMM_SMEM_BYTES>>>(h_p, wqkv_p, bqkv_p, nullptr, qkv_p, NT_, 3 * D_, D_);
    }
    // 4. flash attention (rounded output)
    {
        dim3 grid((S_ + 63) / 64, B_ * H_);
        attn_flash<<<grid, 256, AF_SMEM_BYTES>>>(qkv_p, attn_p);
    }
    // 5. x2 = x + attn @ Wo + bo -> out (full fp32)
    {
        dim3 grid(D_ / GBN, (NT_ + GBM - 1) / GBM);
        sgemm_tc<2, false><<<grid, 128, GEMM_SMEM_BYTES>>>(attn_p, wor_p, bo, x, out, NT_, D_, D_);
    }
    // 6. LN2 (rounded output)
    ln_kernel<<<NT_, 256>>>(out, ln2_g, ln2_b, h_p);
    // 7. ff = gelu(m @ W1 + b1) (rounded output)
    {
        dim3 grid(FF_ / GBN, (NT_ + GBM - 1) / GBM);
        sgemm_tc<1, true><<<grid, 128, GEMM_SMEM_BYTES>>>(h_p, w1r_p, b1, nullptr, ff_p, NT_, FF_, D_);
    }
    // 8. out = x2 + ff @ W2 + b2 (full fp32)
    {
        dim3 grid(D_ / GBN, (NT_ + GBM - 1) / GBM);
        sgemm_tc<2, false><<<grid, 128, GEMM_SMEM_BYTES>>>(ff_p, w2r_p, b2, out, out, NT_, D_, FF_);
    }
}

// round 12
// speedup vs baseline: 1.0629x; 1.0629x over previous
#include <cuda_runtime.h>
#include <cuda_bf16.h>
#include <mma.h>
#include <math.h>

using namespace nvcuda;

#define B_   64
#define S_   577
#define D_   768
#define H_   12
#define DH_  64
#define FF_  3072
#define NT_  (B_ * S_)          // 36928 tokens

// ---------------- scratch ----------------
__device__ float g_h[(size_t)NT_ * D_];
__device__ float g_qkv[(size_t)NT_ * 3 * D_];
__device__ float g_attn[(size_t)NT_ * D_];
__device__ float g_ff[(size_t)NT_ * FF_];
__device__ float g_wqkv[(size_t)D_ * 3 * D_];
__device__ float g_bqkv[3 * D_];
__device__ float g_wor[(size_t)D_ * D_];
__device__ float g_w1r[(size_t)D_ * FF_];
__device__ float g_w2r[(size_t)FF_ * D_];

// ---------------- helpers ----------------
__device__ __forceinline__ float tf32r(float x) { return wmma::__float_to_tf32(x); }

__device__ __forceinline__ float gelu_tanh(float x) {
    const float c = 0.7978845608028654f;
    float x3 = x * x * x;
    return 0.5f * x * (1.0f + tanhf(c * (x + 0.044715f * x3)));
}

__device__ __forceinline__ void cp_async16(float* s, const float* g, bool pred) {
    unsigned saddr = (unsigned)__cvta_generic_to_shared(s);
    int sz = pred ? 16 : 0;
    asm volatile("cp.async.cg.shared.global [%0], [%1], 16, %2;\n"
                 :: "r"(saddr), "l"(g), "r"(sz));
}
__device__ __forceinline__ void cp_commit() { asm volatile("cp.async.commit_group;\n"); }
template <int N>
__device__ __forceinline__ void cp_wait() { asm volatile("cp.async.wait_group %0;\n" :: "n"(N)); }

// ---------------- round-copy (RN tf32) ----------------
__global__ void round_copy_kernel(const float* __restrict__ in, float* __restrict__ out, int n) {
    int i = blockIdx.x * blockDim.x + threadIdx.x;
    if (i < n) out[i] = tf32r(in[i]);
}

// ---------------- pack per-head QKV weights into fused [D, 2304] (rounded) ----------------
__global__ void pack_qkv_kernel(const float* __restrict__ Wq, const float* __restrict__ Wk,
                                const float* __restrict__ Wv, const float* __restrict__ bq,
                                const float* __restrict__ bk, const float* __restrict__ bv) {
    size_t idx = (size_t)blockIdx.x * blockDim.x + threadIdx.x;
    size_t total = (size_t)D_ * 3 * D_;
    if (idx >= total) return;
    int d  = (int)(idx / (3 * D_));
    int j  = (int)(idx % (3 * D_));
    int sel = j / D_;
    int jj  = j % D_;
    int h = jj / DH_;
    int e = jj % DH_;
    const float* W = (sel == 0) ? Wq : (sel == 1) ? Wk : Wv;
    g_wqkv[idx] = tf32r(W[((size_t)h * D_ + d) * DH_ + e]);
    if (d == 0) {
        const float* bb = (sel == 0) ? bq : (sel == 1) ? bk : bv;
        g_bqkv[j] = bb[jj];
    }
}

// ---------------- LayerNorm (tf32-rounded output) ----------------
__global__ __launch_bounds__(256) void ln_kernel(const float* __restrict__ x,
                                                 const float* __restrict__ g,
                                                 const float* __restrict__ bet,
                                                 float* __restrict__ out) {
    int t = blockIdx.x;
    const float* xr = x + (size_t)t * D_;
    float* orow = out + (size_t)t * D_;
    int tid = threadIdx.x;
    float v0 = xr[tid], v1 = xr[tid + 256], v2 = xr[tid + 512];
    float s  = v0 + v1 + v2;
    float ss = v0 * v0 + v1 * v1 + v2 * v2;
    #pragma unroll
    for (int o = 16; o > 0; o >>= 1) {
        s  += __shfl_xor_sync(0xffffffffu, s, o);
        ss += __shfl_xor_sync(0xffffffffu, ss, o);
    }
    __shared__ float sh[16];
    __shared__ float mb[2];
    int w = tid >> 5, lane = tid & 31;
    if (lane == 0) { sh[w] = s; sh[w + 8] = ss; }
    __syncthreads();
    if (tid == 0) {
        float S1 = 0.f, S2 = 0.f;
        #pragma unroll
        for (int i = 0; i < 8; i++) { S1 += sh[i]; S2 += sh[i + 8]; }
        float mean = S1 * (1.0f / D_);
        float var  = S2 * (1.0f / D_) - mean * mean;
        mb[0] = mean;
        mb[1] = rsqrtf(var + 1e-6f);
    }
    __syncthreads();
    float mean = mb[0], rstd = mb[1];
    orow[tid]       = tf32r((v0 - mean) * rstd * g[tid]       + bet[tid]);
    orow[tid + 256] = tf32r((v1 - mean) * rstd * g[tid + 256] + bet[tid + 256]);
    orow[tid + 512] = tf32r((v2 - mean) * rstd * g[tid + 512] + bet[tid + 512]);
}

// ---------------- tf32 SGEMM: 128x128x32, 128 thr (4 warps, 64x64), 3-stage, 2 CTA/SM ----------------
// + software-pipelined fragment loads (double-buffered af/bf)
#define GBM 128
#define GBN 128
#define GBK 32
#define A_LD 36
#define B_LD 132
#define ASZ (GBM * A_LD)
#define BSZ (GBK * B_LD)
#define GEMM_SMEM_FLOATS (3 * ASZ + 3 * BSZ)
#define GEMM_SMEM_BYTES  (GEMM_SMEM_FLOATS * 4)   // 105,984 B

template <int EPI, bool RND>
__global__ __launch_bounds__(128, 2) void sgemm_tc(const float* __restrict__ A,
                                                   const float* __restrict__ Bw,
                                                   const float* __restrict__ bias,
                                                   const float* __restrict__ res,
                                                   float* __restrict__ C,
                                                   int M, int N, int K) {
    extern __shared__ float dsm[];
    float* As = dsm;
    float* Bs = dsm + 3 * ASZ;

    int tid = threadIdx.x;
    int wid = tid >> 5, lane = tid & 31;
    int warp_m = wid & 1;        // 2 x 64 rows
    int warp_n = wid >> 1;       // 2 x 64 cols
    int blockM = blockIdx.y * GBM;
    int blockN = blockIdx.x * GBN;

    int aRow = tid >> 2;          // 0..31 (+32/pass)
    int aCol = (tid & 3) * 8;
    int bRow = tid >> 5;          // 0..3 (+4/pass)
    int bCol = (tid & 31) * 4;

    int nk = K / GBK;

    auto issue_tile = [&](int t, int buf) {
        int k0 = t * GBK;
        float* Ad = As + buf * ASZ;
        float* Bd = Bs + buf * BSZ;
        #pragma unroll
        for (int p = 0; p < 4; p++) {
            int r = aRow + p * 32;
            bool ok = (blockM + r) < M;
            const float* gp = A + (size_t)(ok ? (blockM + r) : 0) * K + k0 + aCol;
            cp_async16(Ad + r * A_LD + aCol,     gp,     ok);
            cp_async16(Ad + r * A_LD + aCol + 4, gp + 4, ok);
        }
        #pragma unroll
        for (int p = 0; p < 8; p++) {
            int r = bRow + p * 4;
            const float* gp = Bw + (size_t)(k0 + r) * N + blockN + bCol;
            cp_async16(Bd + r * B_LD + bCol, gp, true);
        }
    };

    wmma::fragment<wmma::accumulator, 16, 16, 8, float> acc[4][4];
    #pragma unroll
    for (int i = 0; i < 4; i++)
        #pragma unroll
        for (int j = 0; j < 4; j++) wmma::fill_fragment(acc[i][j], 0.0f);

    issue_tile(0, 0); cp_commit();
    issue_tile(1, 1); cp_commit();

    int buf = 0;
    for (int t = 0; t < nk; t++) {
        cp_wait<1>();
        __syncthreads();
        if (t + 2 < nk) { issue_tile(t + 2, (buf + 2) % 3); cp_commit(); }

        float* Ab = As + buf * ASZ;
        float* Bb = Bs + buf * BSZ;

        // double-buffered fragment pipeline over the 4 k-steps
        wmma::fragment<wmma::matrix_a, 16, 16, 8, wmma::precision::tf32, wmma::row_major> af[2][4];
        wmma::fragment<wmma::matrix_b, 16, 16, 8, wmma::precision::tf32, wmma::row_major> bf[2][4];
        #pragma unroll
        for (int i = 0; i < 4; i++)
            wmma::load_matrix_sync(af[0][i], Ab + (warp_m * 64 + i * 16) * A_LD, A_LD);
        #pragma unroll
        for (int j = 0; j < 4; j++)
            wmma::load_matrix_sync(bf[0][j], Bb + warp_n * 64 + j * 16, B_LD);

        #pragma unroll
        for (int ks = 0; ks < 4; ks++) {
            int cur = ks & 1, nxt = cur ^ 1;
            if (ks < 3) {
                #pragma unroll
                for (int i = 0; i < 4; i++)
                    wmma::load_matrix_sync(af[nxt][i],
                        Ab + (warp_m * 64 + i * 16) * A_LD + (ks + 1) * 8, A_LD);
                #pragma unroll
                for (int j = 0; j < 4; j++)
                    wmma::load_matrix_sync(bf[nxt][j],
                        Bb + ((ks + 1) * 8) * B_LD + warp_n * 64 + j * 16, B_LD);
            }
            #pragma unroll
            for (int i = 0; i < 4; i++)
                #pragma unroll
                for (int j = 0; j < 4; j++)
                    wmma::mma_sync(acc[i][j], af[cur][i], bf[cur][j], acc[i][j]);
        }
        buf = (buf + 1) % 3;
    }

    __syncthreads();
    float* st = dsm + wid * 320;
    int r  = lane >> 1;
    int c0 = (lane & 1) * 8;
    #pragma unroll
    for (int i = 0; i < 4; i++) {
        #pragma unroll
        for (int j = 0; j < 4; j++) {
            wmma::store_matrix_sync(st, acc[i][j], 20, wmma::mem_row_major);
            __syncwarp();
            int grow = blockM + warp_m * 64 + i * 16 + r;
            int gcol = blockN + warp_n * 64 + j * 16 + c0;
            if (grow < M) {
                #pragma unroll
                for (int cc = 0; cc < 8; cc++) {
                    float v = st[r * 20 + c0 + cc] + bias[gcol + cc];
                    if (EPI == 1) v = gelu_tanh(v);
                    else if (EPI == 2) v += res[(size_t)grow * N + gcol + cc];
                    if (RND) v = tf32r(v);
                    C[(size_t)grow * N + gcol + cc] = v;
                }
            }
            __syncwarp();
        }
    }
}

// ---------------- flash attention: streaming softmax, 256 thr, 2 CTA/SM (R9, unchanged) ----------------
#define SKT 10
#define TLD 68
#define T_F (64 * TLD)
#define AF_SMEM_FLOATS (5 * T_F + 64)
#define AF_SMEM_BYTES  (AF_SMEM_FLOATS * 4)   // 87,296 B

__global__ __launch_bounds__(256, 2) void attn_flash(const float* __restrict__ qkv,
                                                     float* __restrict__ attn) {
    extern __shared__ float sm[];
    float* qs   = sm;
    float* ks   = sm + T_F;
    float* vs   = sm + 2 * T_F;
    float* ps   = sm + 3 * T_F;
    float* os   = sm + 4 * T_F;
    float* crow = sm + 5 * T_F;

    int bh = blockIdx.y;
    int b = bh / H_, h = bh % H_;
    int qt = blockIdx.x;
    int tid = threadIdx.x;
    int wid = tid >> 5, lane = tid & 31;
    int warp_m  = wid & 3;
    int warp_nh = wid >> 2;

    int lr  = tid >> 2;
    int lc0 = (tid & 3) * 16;

    {
        int gq = qt * 64 + lr;
        bool qok = gq < S_;
        const float* qp = &qkv[((size_t)(b * S_ + (qok ? gq : 0))) * (3 * D_) + h * DH_];
        #pragma unroll
        for (int i = 0; i < 4; i++) {
            float4 v = qok ? *(const float4*)&qp[lc0 + i * 4] : make_float4(0.f, 0.f, 0.f, 0.f);
            *(float4*)&qs[lr * TLD + lc0 + i * 4] = v;
        }
        for (int i = tid; i < T_F; i += 256) os[i] = 0.f;
    }

    float mrow[8], lrow[8];
    #pragma unroll
    for (int rr = 0; rr < 8; rr++) { mrow[rr] = -1e30f; lrow[rr] = 0.f; }

    for (int kt = 0; kt < SKT; kt++) {
        __syncthreads();
        {
            int gk = kt * 64 + lr;
            bool kok = gk < S_;
            const float* kp = &qkv[((size_t)(b * S_ + (kok ? gk : 0))) * (3 * D_) + D_ + h * DH_];
            const float* vp = &qkv[((size_t)(b * S_ + (kok ? gk : 0))) * (3 * D_) + 2 * D_ + h * DH_];
            #pragma unroll
            for (int i = 0; i < 4; i++) {
                float4 kv = kok ? *(const float4*)&kp[lc0 + i * 4] : make_float4(0.f, 0.f, 0.f, 0.f);
                float4 vv = kok ? *(const float4*)&vp[lc0 + i * 4] : make_float4(0.f, 0.f, 0.f, 0.f);
                *(float4*)&ks[lr * TLD + lc0 + i * 4] = kv;
                *(float4*)&vs[lr * TLD + lc0 + i * 4] = vv;
            }
        }
        __syncthreads();

        {
            wmma::fragment<wmma::accumulator, 16, 16, 8, float> sacc[2];
            #pragma unroll
            for (int j = 0; j < 2; j++) wmma::fill_fragment(sacc[j], 0.0f);
            #pragma unroll
            for (int kk = 0; kk < 8; kk++) {
                wmma::fragment<wmma::matrix_a, 16, 16, 8, wmma::precision::tf32, wmma::row_major> af;
                wmma::load_matrix_sync(af, qs + (warp_m * 16) * TLD + kk * 8, TLD);
                #pragma unroll
                for (int j = 0; j < 2; j++) {
                    wmma::fragment<wmma::matrix_b, 16, 16, 8, wmma::precision::tf32, wmma::col_major> bf;
                    wmma::load_matrix_sync(bf, ks + (warp_nh * 32 + j * 16) * TLD + kk * 8, TLD);
                    wmma::mma_sync(sacc[j], af, bf, sacc[j]);
                }
            }
            #pragma unroll
            for (int j = 0; j < 2; j++) {
                #pragma unroll
                for (int e = 0; e < sacc[j].num_elements; e++) sacc[j].x[e] *= 0.125f;
                wmma::store_matrix_sync(ps + (warp_m * 16) * TLD + warp_nh * 32 + j * 16,
                                        sacc[j], TLD, wmma::mem_row_major);
            }
        }
        __syncthreads();

        #pragma unroll
        for (int rr = 0; rr < 8; rr++) {
            int r = wid * 8 + rr;
            float* row = ps + r * TLD;
            int gc0 = kt * 64 + lane;
            int gc1 = gc0 + 32;
            float a0 = (gc0 < S_) ? row[lane]      : -1e30f;
            float a1 = (gc1 < S_) ? row[lane + 32] : -1e30f;
            float tmax = fmaxf(a0, a1);
            #pragma unroll
            for (int o = 16; o > 0; o >>= 1) tmax = fmaxf(tmax, __shfl_xor_sync(0xffffffffu, tmax, o));
            float m_new = fmaxf(mrow[rr], tmax);
            float corr = __expf(mrow[rr] - m_new);
            float p0 = (gc0 < S_) ? __expf(a0 - m_new) : 0.f;
            float p1 = (gc1 < S_) ? __expf(a1 - m_new) : 0.f;
            float tsum = p0 + p1;
            #pragma unroll
            for (int o = 16; o > 0; o >>= 1) tsum += __shfl_xor_sync(0xffffffffu, tsum, o);
            lrow[rr] = lrow[rr] * corr + tsum;
            mrow[rr] = m_new;
            row[lane]      = tf32r(p0);
            row[lane + 32] = tf32r(p1);
            if (lane == 0) crow[r] = corr;
        }
        __syncthreads();

        {
            float c = crow[lr];
            #pragma unroll
            for (int i = 0; i < 16; i++) os[lr * TLD + lc0 + i] *= c;
        }
        __syncthreads();

        {
            wmma::fragment<wmma::accumulator, 16, 16, 8, float> oacc[2];
            #pragma unroll
            for (int j = 0; j < 2; j++)
                wmma::load_matrix_sync(oacc[j], os + (warp_m * 16) * TLD + warp_nh * 32 + j * 16,
                                       TLD, wmma::mem_row_major);
            #pragma unroll
            for (int kk = 0; kk < 8; kk++) {
                wmma::fragment<wmma::matrix_a, 16, 16, 8, wmma::precision::tf32, wmma::row_major> af;
                wmma::load_matrix_sync(af, ps + (warp_m * 16) * TLD + kk * 8, TLD);
                #pragma unroll
                for (int j = 0; j < 2; j++) {
                    wmma::fragment<wmma::matrix_b, 16, 16, 8, wmma::precision::tf32, wmma::row_major> bf;
                    wmma::load_matrix_sync(bf, vs + (kk * 8) * TLD + warp_nh * 32 + j * 16, TLD);
                    wmma::mma_sync(oacc[j], af, bf, oacc[j]);
                }
            }
            #pragma unroll
            for (int j = 0; j < 2; j++)
                wmma::store_matrix_sync(os + (warp_m * 16) * TLD + warp_nh * 32 + j * 16,
                                        oacc[j], TLD, wmma::mem_row_major);
        }
    }
    __syncthreads();

    #pragma unroll
    for (int rr = 0; rr < 8; rr++) {
        int rloc = wid * 8 + rr;
        int gi = qt * 64 + rloc;
        if (gi >= S_) continue;
        float linv = 1.0f / lrow[rr];
        float* orow = &attn[((size_t)(b * S_ + gi)) * D_ + h * DH_];
        int c = lane * 2;
        orow[c]     = tf32r(os[rloc * TLD + c] * linv);
        orow[c + 1] = tf32r(os[rloc * TLD + c + 1] * linv);
    }
}

// ---------------- launch ----------------
extern "C" void kernel_launch(void* const* d_in, const int* in_sizes, int n_in,
                              void* d_out, int out_size) {
    const float* x     = (const float*)d_in[0];
    const float* ln1_g = (const float*)d_in[1];
    const float* ln1_b = (const float*)d_in[2];
    const float* Wq    = (const float*)d_in[3];
    const float* bq    = (const float*)d_in[4];
    const float* Wk    = (const float*)d_in[5];
    const float* bk    = (const float*)d_in[6];
    const float* Wv    = (const float*)d_in[7];
    const float* bv    = (const float*)d_in[8];
    const float* Wo    = (const float*)d_in[9];
    const float* bo    = (const float*)d_in[10];
    const float* ln2_g = (const float*)d_in[11];
    const float* ln2_b = (const float*)d_in[12];
    const float* W1    = (const float*)d_in[13];
    const float* b1    = (const float*)d_in[14];
    const float* W2    = (const float*)d_in[15];
    const float* b2    = (const float*)d_in[16];
    float* out = (float*)d_out;

    float* h_p;    cudaGetSymbolAddress((void**)&h_p, g_h);
    float* qkv_p;  cudaGetSymbolAddress((void**)&qkv_p, g_qkv);
    float* attn_p; cudaGetSymbolAddress((void**)&attn_p, g_attn);
    float* ff_p;   cudaGetSymbolAddress((void**)&ff_p, g_ff);
    float* wqkv_p; cudaGetSymbolAddress((void**)&wqkv_p, g_wqkv);
    float* bqkv_p; cudaGetSymbolAddress((void**)&bqkv_p, g_bqkv);
    float* wor_p;  cudaGetSymbolAddress((void**)&wor_p, g_wor);
    float* w1r_p;  cudaGetSymbolAddress((void**)&w1r_p, g_w1r);
    float* w2r_p;  cudaGetSymbolAddress((void**)&w2r_p, g_w2r);

    cudaFuncSetAttribute((const void*)sgemm_tc<0, true>,  cudaFuncAttributeMaxDynamicSharedMemorySize, GEMM_SMEM_BYTES);
    cudaFuncSetAttribute((const void*)sgemm_tc<1, true>,  cudaFuncAttributeMaxDynamicSharedMemorySize, GEMM_SMEM_BYTES);
    cudaFuncSetAttribute((const void*)sgemm_tc<2, false>, cudaFuncAttributeMaxDynamicSharedMemorySize, GEMM_SMEM_BYTES);
    cudaFuncSetAttribute((const void*)attn_flash, cudaFuncAttributeMaxDynamicSharedMemorySize, AF_SMEM_BYTES);

    // 0. round weight copies (RN tf32)
    {
        int n1 = D_ * D_;
        round_copy_kernel<<<(n1 + 255) / 256, 256>>>(Wo, wor_p, n1);
        int n2 = D_ * FF_;
        round_copy_kernel<<<(n2 + 255) / 256, 256>>>(W1, w1r_p, n2);
        round_copy_kernel<<<(n2 + 255) / 256, 256>>>(W2, w2r_p, n2);
    }
    // 1. pack fused QKV weights (rounded)
    {
        size_t total = (size_t)D_ * 3 * D_;
        pack_qkv_kernel<<<(int)((total + 255) / 256), 256>>>(Wq, Wk, Wv, bq, bk, bv);
    }
    // 2. LN1 (rounded output)
    ln_kernel<<<NT_, 256>>>(x, ln1_g, ln1_b, h_p);
    // 3. fused QKV GEMM (rounded output)
    {
        dim3 grid(3 * D_ / GBN, (NT_ + GBM - 1) / GBM);
        sgemm_tc<0, true><<<grid, 128, GEMM_SMEM_BYTES>>>(h_p, wqkv_p, bqkv_p, nullptr, qkv_p, NT_, 3 * D_, D_);
    }
    // 4. flash attention (rounded output)
    {
        dim3 grid((S_ + 63) / 64, B_ * H_);
        attn_flash<<<grid, 256, AF_SMEM_BYTES>>>(qkv_p, attn_p);
    }
    // 5. x2 = x + attn @ Wo + bo -> out (full fp32)
    {
        dim3 grid(D_ / GBN, (NT_ + GBM - 1) / GBM);
        sgemm_tc<2, false><<<grid, 128, GEMM_SMEM_BYTES>>>(attn_p, wor_p, bo, x, out, NT_, D_, D_);
    }
    // 6. LN2 (rounded output)
    ln_kernel<<<NT_, 256>>>(out, ln2_g, ln2_b, h_p);
    // 7. ff = gelu(m @ W1 + b1) (rounded output)
    {
        dim3 grid(FF_ / GBN, (NT_ + GBM - 1) / GBM);
        sgemm_tc<1, true><<<grid, 128, GEMM_SMEM_BYTES>>>(h_p, w1r_p, b1, nullptr, ff_p, NT_, FF_, D_);
    }
    // 8. out = x2 + ff @ W2 + b2 (full fp32)
    {
        dim3 grid(D_ / GBN, (NT_ + GBM - 1) / GBM);
        sgemm_tc<2, false><<<grid, 128, GEMM_SMEM_BYTES>>>(ff_p, w2r_p, b2, out, out, NT_, D_, FF_);
    }
}

// round 13
// speedup vs baseline: 1.0674x; 1.0042x over previous
#include <cuda_runtime.h>
#include <cuda_bf16.h>
#include <mma.h>
#include <math.h>

using namespace nvcuda;

#define B_   64
#define S_   577
#define D_   768
#define H_   12
#define DH_  64
#define FF_  3072
#define NT_  (B_ * S_)          // 36928 tokens

// ---------------- scratch ----------------
__device__ float g_h[(size_t)NT_ * D_];
__device__ float g_qkv[(size_t)NT_ * 3 * D_];
__device__ float g_attn[(size_t)NT_ * D_];
__device__ float g_ff[(size_t)NT_ * FF_];
__device__ float g_wqkv[(size_t)D_ * 3 * D_];
__device__ float g_bqkv[3 * D_];
__device__ float g_wor[(size_t)D_ * D_];
__device__ float g_w1r[(size_t)D_ * FF_];
__device__ float g_w2r[(size_t)FF_ * D_];

// ---------------- helpers ----------------
__device__ __forceinline__ float tf32r(float x) { return wmma::__float_to_tf32(x); }

__device__ __forceinline__ float gelu_tanh(float x) {
    const float c = 0.7978845608028654f;
    float x3 = x * x * x;
    return 0.5f * x * (1.0f + tanhf(c * (x + 0.044715f * x3)));
}

__device__ __forceinline__ void cp_async16(float* s, const float* g, bool pred) {
    unsigned saddr = (unsigned)__cvta_generic_to_shared(s);
    int sz = pred ? 16 : 0;
    asm volatile("cp.async.cg.shared.global [%0], [%1], 16, %2;\n"
                 :: "r"(saddr), "l"(g), "r"(sz));
}
__device__ __forceinline__ void cp_commit() { asm volatile("cp.async.commit_group;\n"); }
template <int N>
__device__ __forceinline__ void cp_wait() { asm volatile("cp.async.wait_group %0;\n" :: "n"(N)); }

// ---------------- merged round-copy (RN tf32) for Wo|W1|W2 ----------------
#define N_WO (D_ * D_)
#define N_WF (D_ * FF_)
__global__ void round_copy3_kernel(const float* __restrict__ Wo, const float* __restrict__ W1,
                                   const float* __restrict__ W2) {
    int i = blockIdx.x * blockDim.x + threadIdx.x;
    if (i < N_WO) {
        g_wor[i] = tf32r(Wo[i]);
    }
    if (i < N_WF) {
        g_w1r[i] = tf32r(W1[i]);
        g_w2r[i] = tf32r(W2[i]);
    }
}

// ---------------- pack per-head QKV weights into fused [D, 2304] (rounded) ----------------
__global__ void pack_qkv_kernel(const float* __restrict__ Wq, const float* __restrict__ Wk,
                                const float* __restrict__ Wv, const float* __restrict__ bq,
                                const float* __restrict__ bk, const float* __restrict__ bv) {
    size_t idx = (size_t)blockIdx.x * blockDim.x + threadIdx.x;
    size_t total = (size_t)D_ * 3 * D_;
    if (idx >= total) return;
    int d  = (int)(idx / (3 * D_));
    int j  = (int)(idx % (3 * D_));
    int sel = j / D_;
    int jj  = j % D_;
    int h = jj / DH_;
    int e = jj % DH_;
    const float* W = (sel == 0) ? Wq : (sel == 1) ? Wk : Wv;
    g_wqkv[idx] = tf32r(W[((size_t)h * D_ + d) * DH_ + e]);
    if (d == 0) {
        const float* bb = (sel == 0) ? bq : (sel == 1) ? bk : bv;
        g_bqkv[j] = bb[jj];
    }
}

// ---------------- LayerNorm (tf32-rounded output) ----------------
__global__ __launch_bounds__(256) void ln_kernel(const float* __restrict__ x,
                                                 const float* __restrict__ g,
                                                 const float* __restrict__ bet,
                                                 float* __restrict__ out) {
    int t = blockIdx.x;
    const float* xr = x + (size_t)t * D_;
    float* orow = out + (size_t)t * D_;
    int tid = threadIdx.x;
    float v0 = xr[tid], v1 = xr[tid + 256], v2 = xr[tid + 512];
    float s  = v0 + v1 + v2;
    float ss = v0 * v0 + v1 * v1 + v2 * v2;
    #pragma unroll
    for (int o = 16; o > 0; o >>= 1) {
        s  += __shfl_xor_sync(0xffffffffu, s, o);
        ss += __shfl_xor_sync(0xffffffffu, ss, o);
    }
    __shared__ float sh[16];
    __shared__ float mb[2];
    int w = tid >> 5, lane = tid & 31;
    if (lane == 0) { sh[w] = s; sh[w + 8] = ss; }
    __syncthreads();
    if (tid == 0) {
        float S1 = 0.f, S2 = 0.f;
        #pragma unroll
        for (int i = 0; i < 8; i++) { S1 += sh[i]; S2 += sh[i + 8]; }
        float mean = S1 * (1.0f / D_);
        float var  = S2 * (1.0f / D_) - mean * mean;
        mb[0] = mean;
        mb[1] = rsqrtf(var + 1e-6f);
    }
    __syncthreads();
    float mean = mb[0], rstd = mb[1];
    orow[tid]       = tf32r((v0 - mean) * rstd * g[tid]       + bet[tid]);
    orow[tid + 256] = tf32r((v1 - mean) * rstd * g[tid + 256] + bet[tid + 256]);
    orow[tid + 512] = tf32r((v2 - mean) * rstd * g[tid + 512] + bet[tid + 512]);
}

// ---------------- tf32 SGEMM: 128x128x32, 128 thr (4 warps, 64x64), 3-stage, 2 CTA/SM ----------------
// + software-pipelined fragment loads (R12, unchanged)
#define GBM 128
#define GBN 128
#define GBK 32
#define A_LD 36
#define B_LD 132
#define ASZ (GBM * A_LD)
#define BSZ (GBK * B_LD)
#define GEMM_SMEM_FLOATS (3 * ASZ + 3 * BSZ)
#define GEMM_SMEM_BYTES  (GEMM_SMEM_FLOATS * 4)   // 105,984 B

template <int EPI, bool RND>
__global__ __launch_bounds__(128, 2) void sgemm_tc(const float* __restrict__ A,
                                                   const float* __restrict__ Bw,
                                                   const float* __restrict__ bias,
                                                   const float* __restrict__ res,
                                                   float* __restrict__ C,
                                                   int M, int N, int K) {
    extern __shared__ float dsm[];
    float* As = dsm;
    float* Bs = dsm + 3 * ASZ;

    int tid = threadIdx.x;
    int wid = tid >> 5, lane = tid & 31;
    int warp_m = wid & 1;
    int warp_n = wid >> 1;
    int blockM = blockIdx.y * GBM;
    int blockN = blockIdx.x * GBN;

    int aRow = tid >> 2;
    int aCol = (tid & 3) * 8;
    int bRow = tid >> 5;
    int bCol = (tid & 31) * 4;

    int nk = K / GBK;

    auto issue_tile = [&](int t, int buf) {
        int k0 = t * GBK;
        float* Ad = As + buf * ASZ;
        float* Bd = Bs + buf * BSZ;
        #pragma unroll
        for (int p = 0; p < 4; p++) {
            int r = aRow + p * 32;
            bool ok = (blockM + r) < M;
            const float* gp = A + (size_t)(ok ? (blockM + r) : 0) * K + k0 + aCol;
            cp_async16(Ad + r * A_LD + aCol,     gp,     ok);
            cp_async16(Ad + r * A_LD + aCol + 4, gp + 4, ok);
        }
        #pragma unroll
        for (int p = 0; p < 8; p++) {
            int r = bRow + p * 4;
            const float* gp = Bw + (size_t)(k0 + r) * N + blockN + bCol;
            cp_async16(Bd + r * B_LD + bCol, gp, true);
        }
    };

    wmma::fragment<wmma::accumulator, 16, 16, 8, float> acc[4][4];
    #pragma unroll
    for (int i = 0; i < 4; i++)
        #pragma unroll
        for (int j = 0; j < 4; j++) wmma::fill_fragment(acc[i][j], 0.0f);

    issue_tile(0, 0); cp_commit();
    issue_tile(1, 1); cp_commit();

    int buf = 0;
    for (int t = 0; t < nk; t++) {
        cp_wait<1>();
        __syncthreads();
        if (t + 2 < nk) { issue_tile(t + 2, (buf + 2) % 3); cp_commit(); }

        float* Ab = As + buf * ASZ;
        float* Bb = Bs + buf * BSZ;

        wmma::fragment<wmma::matrix_a, 16, 16, 8, wmma::precision::tf32, wmma::row_major> af[2][4];
        wmma::fragment<wmma::matrix_b, 16, 16, 8, wmma::precision::tf32, wmma::row_major> bf[2][4];
        #pragma unroll
        for (int i = 0; i < 4; i++)
            wmma::load_matrix_sync(af[0][i], Ab + (warp_m * 64 + i * 16) * A_LD, A_LD);
        #pragma unroll
        for (int j = 0; j < 4; j++)
            wmma::load_matrix_sync(bf[0][j], Bb + warp_n * 64 + j * 16, B_LD);

        #pragma unroll
        for (int ks = 0; ks < 4; ks++) {
            int cur = ks & 1, nxt = cur ^ 1;
            if (ks < 3) {
                #pragma unroll
                for (int i = 0; i < 4; i++)
                    wmma::load_matrix_sync(af[nxt][i],
                        Ab + (warp_m * 64 + i * 16) * A_LD + (ks + 1) * 8, A_LD);
                #pragma unroll
                for (int j = 0; j < 4; j++)
                    wmma::load_matrix_sync(bf[nxt][j],
                        Bb + ((ks + 1) * 8) * B_LD + warp_n * 64 + j * 16, B_LD);
            }
            #pragma unroll
            for (int i = 0; i < 4; i++)
                #pragma unroll
                for (int j = 0; j < 4; j++)
                    wmma::mma_sync(acc[i][j], af[cur][i], bf[cur][j], acc[i][j]);
        }
        buf = (buf + 1) % 3;
    }

    __syncthreads();
    float* st = dsm + wid * 320;
    int r  = lane >> 1;
    int c0 = (lane & 1) * 8;
    #pragma unroll
    for (int i = 0; i < 4; i++) {
        #pragma unroll
        for (int j = 0; j < 4; j++) {
            wmma::store_matrix_sync(st, acc[i][j], 20, wmma::mem_row_major);
            __syncwarp();
            int grow = blockM + warp_m * 64 + i * 16 + r;
            int gcol = blockN + warp_n * 64 + j * 16 + c0;
            if (grow < M) {
                #pragma unroll
                for (int cc = 0; cc < 8; cc++) {
                    float v = st[r * 20 + c0 + cc] + bias[gcol + cc];
                    if (EPI == 1) v = gelu_tanh(v);
                    else if (EPI == 2) v += res[(size_t)grow * N + gcol + cc];
                    if (RND) v = tf32r(v);
                    C[(size_t)grow * N + gcol + cc] = v;
                }
            }
            __syncwarp();
        }
    }
}

// ---------------- flash attention: 128-row Q tile, 512 thr / 16 warps, 1 CTA/SM ----------------
#define SKT 10
#define TLD 68
#define QROWS 128
#define QS_F  (QROWS * TLD)            // 8704
#define KV_F  (64 * TLD)               // 4352
#define AF_SMEM_FLOATS (QS_F * 3 + KV_F * 2 + QROWS)   // qs, ps, os, ks, vs, crow
#define AF_SMEM_BYTES  (AF_SMEM_FLOATS * 4)            // 139,776 B

__global__ __launch_bounds__(512, 1) void attn_flash(const float* __restrict__ qkv,
                                                     float* __restrict__ attn) {
    extern __shared__ float sm[];
    float* qs   = sm;                         // [128][68]
    float* ps   = sm + QS_F;                  // [128][68]
    float* os   = sm + 2 * QS_F;              // [128][68]
    float* ks   = sm + 3 * QS_F;              // [64][68]
    float* vs   = sm + 3 * QS_F + KV_F;       // [64][68]
    float* crow = sm + 3 * QS_F + 2 * KV_F;   // [128]

    int bh = blockIdx.y;
    int b = bh / H_, h = bh % H_;
    int qt = blockIdx.x;
    int tid = threadIdx.x;
    int wid = tid >> 5, lane = tid & 31;
    int warp_m  = wid & 7;          // 8 x 16 rows
    int warp_nh = wid >> 3;         // 2 x 32 cols

    int lr  = tid >> 2;             // 0..127
    int lc0 = (tid & 3) * 16;
    int kvr = tid >> 3;             // 0..63
    int kvc = (tid & 7) * 8;

    // load Q tile [128][64], zero O
    {
        int gq = qt * QROWS + lr;
        bool qok = gq < S_;
        const float* qp = &qkv[((size_t)(b * S_ + (qok ? gq : 0))) * (3 * D_) + h * DH_];
        #pragma unroll
        for (int i = 0; i < 4; i++) {
            float4 v = qok ? *(const float4*)&qp[lc0 + i * 4] : make_float4(0.f, 0.f, 0.f, 0.f);
            *(float4*)&qs[lr * TLD + lc0 + i * 4] = v;
        }
        for (int i = tid; i < QS_F; i += 512) os[i] = 0.f;
    }

    float mrow[8], lrow[8];
    #pragma unroll
    for (int rr = 0; rr < 8; rr++) { mrow[rr] = -1e30f; lrow[rr] = 0.f; }

    for (int kt = 0; kt < SKT; kt++) {
        __syncthreads();
        {
            int gk = kt * 64 + kvr;
            bool kok = gk < S_;
            const float* kp = &qkv[((size_t)(b * S_ + (kok ? gk : 0))) * (3 * D_) + D_ + h * DH_];
            const float* vp = &qkv[((size_t)(b * S_ + (kok ? gk : 0))) * (3 * D_) + 2 * D_ + h * DH_];
            float4 k0 = kok ? *(const float4*)&kp[kvc]     : make_float4(0.f, 0.f, 0.f, 0.f);
            float4 k1 = kok ? *(const float4*)&kp[kvc + 4] : make_float4(0.f, 0.f, 0.f, 0.f);
            float4 v0 = kok ? *(const float4*)&vp[kvc]     : make_float4(0.f, 0.f, 0.f, 0.f);
            float4 v1 = kok ? *(const float4*)&vp[kvc + 4] : make_float4(0.f, 0.f, 0.f, 0.f);
            *(float4*)&ks[kvr * TLD + kvc]     = k0;
            *(float4*)&ks[kvr * TLD + kvc + 4] = k1;
            *(float4*)&vs[kvr * TLD + kvc]     = v0;
            *(float4*)&vs[kvr * TLD + kvc + 4] = v1;
        }
        __syncthreads();

        // S = Q K^T / 8 -> ps [128][64]
        {
            wmma::fragment<wmma::accumulator, 16, 16, 8, float> sacc[2];
            #pragma unroll
            for (int j = 0; j < 2; j++) wmma::fill_fragment(sacc[j], 0.0f);
            #pragma unroll
            for (int kk = 0; kk < 8; kk++) {
                wmma::fragment<wmma::matrix_a, 16, 16, 8, wmma::precision::tf32, wmma::row_major> af;
                wmma::load_matrix_sync(af, qs + (warp_m * 16) * TLD + kk * 8, TLD);
                #pragma unroll
                for (int j = 0; j < 2; j++) {
                    wmma::fragment<wmma::matrix_b, 16, 16, 8, wmma::precision::tf32, wmma::col_major> bf;
                    wmma::load_matrix_sync(bf, ks + (warp_nh * 32 + j * 16) * TLD + kk * 8, TLD);
                    wmma::mma_sync(sacc[j], af, bf, sacc[j]);
                }
            }
            #pragma unroll
            for (int j = 0; j < 2; j++) {
                #pragma unroll
                for (int e = 0; e < sacc[j].num_elements; e++) sacc[j].x[e] *= 0.125f;
                wmma::store_matrix_sync(ps + (warp_m * 16) * TLD + warp_nh * 32 + j * 16,
                                        sacc[j], TLD, wmma::mem_row_major);
            }
        }
        __syncthreads();

        // streaming softmax: warp wid owns rows wid*8 .. wid*8+7 (16 warps x 8 = 128)
        #pragma unroll
        for (int rr = 0; rr < 8; rr++) {
            int r = wid * 8 + rr;
            float* row = ps + r * TLD;
            int gc0 = kt * 64 + lane;
            int gc1 = gc0 + 32;
            float a0 = (gc0 < S_) ? row[lane]      : -1e30f;
            float a1 = (gc1 < S_) ? row[lane + 32] : -1e30f;
            float tmax = fmaxf(a0, a1);
            #pragma unroll
            for (int o = 16; o > 0; o >>= 1) tmax = fmaxf(tmax, __shfl_xor_sync(0xffffffffu, tmax, o));
            float m_new = fmaxf(mrow[rr], tmax);
            float corr = __expf(mrow[rr] - m_new);
            float p0 = (gc0 < S_) ? __expf(a0 - m_new) : 0.f;
            float p1 = (gc1 < S_) ? __expf(a1 - m_new) : 0.f;
            float tsum = p0 + p1;
            #pragma unroll
            for (int o = 16; o > 0; o >>= 1) tsum += __shfl_xor_sync(0xffffffffu, tsum, o);
            lrow[rr] = lrow[rr] * corr + tsum;
            mrow[rr] = m_new;
            row[lane]      = tf32r(p0);
            row[lane + 32] = tf32r(p1);
            if (lane == 0) crow[r] = corr;
        }
        __syncthreads();

        // rescale O
        {
            float c = crow[lr];
            #pragma unroll
            for (int i = 0; i < 16; i++) os[lr * TLD + lc0 + i] *= c;
        }
        __syncthreads();

        // O += P V
        {
            wmma::fragment<wmma::accumulator, 16, 16, 8, float> oacc[2];
            #pragma unroll
            for (int j = 0; j < 2; j++)
                wmma::load_matrix_sync(oacc[j], os + (warp_m * 16) * TLD + warp_nh * 32 + j * 16,
                                       TLD, wmma::mem_row_major);
            #pragma unroll
            for (int kk = 0; kk < 8; kk++) {
                wmma::fragment<wmma::matrix_a, 16, 16, 8, wmma::precision::tf32, wmma::row_major> af;
                wmma::load_matrix_sync(af, ps + (warp_m * 16) * TLD + kk * 8, TLD);
                #pragma unroll
                for (int j = 0; j < 2; j++) {
                    wmma::fragment<wmma::matrix_b, 16, 16, 8, wmma::precision::tf32, wmma::row_major> bf;
                    wmma::load_matrix_sync(bf, vs + (kk * 8) * TLD + warp_nh * 32 + j * 16, TLD);
                    wmma::mma_sync(oacc[j], af, bf, oacc[j]);
                }
            }
            #pragma unroll
            for (int j = 0; j < 2; j++)
                wmma::store_matrix_sync(os + (warp_m * 16) * TLD + warp_nh * 32 + j * 16,
                                        oacc[j], TLD, wmma::mem_row_major);
        }
    }
    __syncthreads();

    // epilogue: warp wid rows wid*8..+7, divide by l, write (tf32-rounded)
    #pragma unroll
    for (int rr = 0; rr < 8; rr++) {
        int rloc = wid * 8 + rr;
        int gi = qt * QROWS + rloc;
        if (gi >= S_) continue;
        float linv = 1.0f / lrow[rr];
        float* orow = &attn[((size_t)(b * S_ + gi)) * D_ + h * DH_];
        int c = lane * 2;
        orow[c]     = tf32r(os[rloc * TLD + c] * linv);
        orow[c + 1] = tf32r(os[rloc * TLD + c + 1] * linv);
    }
}

// ---------------- launch ----------------
extern "C" void kernel_launch(void* const* d_in, const int* in_sizes, int n_in,
                              void* d_out, int out_size) {
    const float* x     = (const float*)d_in[0];
    const float* ln1_g = (const float*)d_in[1];
    const float* ln1_b = (const float*)d_in[2];
    const float* Wq    = (const float*)d_in[3];
    const float* bq    = (const float*)d_in[4];
    const float* Wk    = (const float*)d_in[5];
    const float* bk    = (const float*)d_in[6];
    const float* Wv    = (const float*)d_in[7];
    const float* bv    = (const float*)d_in[8];
    const float* Wo    = (const float*)d_in[9];
    const float* bo    = (const float*)d_in[10];
    const float* ln2_g = (const float*)d_in[11];
    const float* ln2_b = (const float*)d_in[12];
    const float* W1    = (const float*)d_in[13];
    const float* b1    = (const float*)d_in[14];
    const float* W2    = (const float*)d_in[15];
    const float* b2    = (const float*)d_in[16];
    float* out = (float*)d_out;

    float* h_p;    cudaGetSymbolAddress((void**)&h_p, g_h);
    float* qkv_p;  cudaGetSymbolAddress((void**)&qkv_p, g_qkv);
    float* attn_p; cudaGetSymbolAddress((void**)&attn_p, g_attn);
    float* ff_p;   cudaGetSymbolAddress((void**)&ff_p, g_ff);
    float* wqkv_p; cudaGetSymbolAddress((void**)&wqkv_p, g_wqkv);
    float* bqkv_p; cudaGetSymbolAddress((void**)&bqkv_p, g_bqkv);
    float* wor_p;  cudaGetSymbolAddress((void**)&wor_p, g_wor);
    float* w1r_p;  cudaGetSymbolAddress((void**)&w1r_p, g_w1r);
    float* w2r_p;  cudaGetSymbolAddress((void**)&w2r_p, g_w2r);

    cudaFuncSetAttribute((const void*)sgemm_tc<0, true>,  cudaFuncAttributeMaxDynamicSharedMemorySize, GEMM_SMEM_BYTES);
    cudaFuncSetAttribute((const void*)sgemm_tc<1, true>,  cudaFuncAttributeMaxDynamicSharedMemorySize, GEMM_SMEM_BYTES);
    cudaFuncSetAttribute((const void*)sgemm_tc<2, false>, cudaFuncAttributeMaxDynamicSharedMemorySize, GEMM_SMEM_BYTES);
    cudaFuncSetAttribute((const void*)attn_flash, cudaFuncAttributeMaxDynamicSharedMemorySize, AF_SMEM_BYTES);

    // 0. weight prep (merged round copies + pack)
    round_copy3_kernel<<<(N_WF + 255) / 256, 256>>>(Wo, W1, W2);
    {
        size_t total = (size_t)D_ * 3 * D_;
        pack_qkv_kernel<<<(int)((total + 255) / 256), 256>>>(Wq, Wk, Wv, bq, bk, bv);
    }
    // 1. LN1 (rounded output)
    ln_kernel<<<NT_, 256>>>(x, ln1_g, ln1_b, h_p);
    // 2. fused QKV GEMM (rounded output)
    {
        dim3 grid(3 * D_ / GBN, (NT_ + GBM - 1) / GBM);
        sgemm_tc<0, true><<<grid, 128, GEMM_SMEM_BYTES>>>(h_p, wqkv_p, bqkv_p, nullptr, qkv_p, NT_, 3 * D_, D_);
    }
    // 3. flash attention (128-row Q tiles)
    {
        dim3 grid((S_ + QROWS - 1) / QROWS, B_ * H_);
        attn_flash<<<grid, 512, AF_SMEM_BYTES>>>(qkv_p, attn_p);
    }
    // 4. x2 = x + attn @ Wo + bo -> out (full fp32)
    {
        dim3 grid(D_ / GBN, (NT_ + GBM - 1) / GBM);
        sgemm_tc<2, false><<<grid, 128, GEMM_SMEM_BYTES>>>(attn_p, wor_p, bo, x, out, NT_, D_, D_);
    }
    // 5. LN2 (rounded output)
    ln_kernel<<<NT_, 256>>>(out, ln2_g, ln2_b, h_p);
    // 6. ff = gelu(m @ W1 + b1) (rounded output)
    {
        dim3 grid(FF_ / GBN, (NT_ + GBM - 1) / GBM);
        sgemm_tc<1, true><<<grid, 128, GEMM_SMEM_BYTES>>>(h_p, w1r_p, b1, nullptr, ff_p, NT_, FF_, D_);
    }
    // 7. out = x2 + ff @ W2 + b2 (full fp32)
    {
        dim3 grid(D_ / GBN, (NT_ + GBM - 1) / GBM);
        sgemm_tc<2, false><<<grid, 128, GEMM_SMEM_BYTES>>>(ff_p, w2r_p, b2, out, out, NT_, D_, FF_);
    }
}

// round 15
// speedup vs baseline: 1.0720x; 1.0043x over previous
#include <cuda_runtime.h>
#include <cuda_bf16.h>
#include <mma.h>
#include <math.h>

using namespace nvcuda;

#define B_   64
#define S_   577
#define D_   768
#define H_   12
#define DH_  64
#define FF_  3072
#define NT_  (B_ * S_)          // 36928 tokens

// ---------------- scratch ----------------
__device__ float g_h[(size_t)NT_ * D_];
__device__ float g_qkv[(size_t)NT_ * 3 * D_];
__device__ float g_attn[(size_t)NT_ * D_];
__device__ float g_ff[(size_t)NT_ * FF_];
__device__ float g_wqkv[(size_t)D_ * 3 * D_];
__device__ float g_bqkv[3 * D_];
__device__ float g_wor[(size_t)D_ * D_];
__device__ float g_w1r[(size_t)D_ * FF_];
__device__ float g_w2r[(size_t)FF_ * D_];

// ---------------- helpers ----------------
__device__ __forceinline__ float tf32r(float x) { return wmma::__float_to_tf32(x); }

__device__ __forceinline__ float gelu_tanh(float x) {
    const float c = 0.7978845608028654f;
    float x3 = x * x * x;
    return 0.5f * x * (1.0f + tanhf(c * (x + 0.044715f * x3)));
}

__device__ __forceinline__ void cp_async16(float* s, const float* g, bool pred) {
    unsigned saddr = (unsigned)__cvta_generic_to_shared(s);
    int sz = pred ? 16 : 0;
    asm volatile("cp.async.cg.shared.global [%0], [%1], 16, %2;\n"
                 :: "r"(saddr), "l"(g), "r"(sz));
}
__device__ __forceinline__ void cp_commit() { asm volatile("cp.async.commit_group;\n"); }
template <int N>
__device__ __forceinline__ void cp_wait() { asm volatile("cp.async.wait_group %0;\n" :: "n"(N)); }

// ---------------- merged round-copy (RN tf32) for Wo|W1|W2 ----------------
#define N_WO (D_ * D_)
#define N_WF (D_ * FF_)
__global__ void round_copy3_kernel(const float* __restrict__ Wo, const float* __restrict__ W1,
                                   const float* __restrict__ W2) {
    int i = blockIdx.x * blockDim.x + threadIdx.x;
    if (i < N_WO) {
        g_wor[i] = tf32r(Wo[i]);
    }
    if (i < N_WF) {
        g_w1r[i] = tf32r(W1[i]);
        g_w2r[i] = tf32r(W2[i]);
    }
}

// ---------------- pack per-head QKV weights into fused [D, 2304] (rounded) ----------------
__global__ void pack_qkv_kernel(const float* __restrict__ Wq, const float* __restrict__ Wk,
                                const float* __restrict__ Wv, const float* __restrict__ bq,
                                const float* __restrict__ bk, const float* __restrict__ bv) {
    size_t idx = (size_t)blockIdx.x * blockDim.x + threadIdx.x;
    size_t total = (size_t)D_ * 3 * D_;
    if (idx >= total) return;
    int d  = (int)(idx / (3 * D_));
    int j  = (int)(idx % (3 * D_));
    int sel = j / D_;
    int jj  = j % D_;
    int h = jj / DH_;
    int e = jj % DH_;
    const float* W = (sel == 0) ? Wq : (sel == 1) ? Wk : Wv;
    g_wqkv[idx] = tf32r(W[((size_t)h * D_ + d) * DH_ + e]);
    if (d == 0) {
        const float* bb = (sel == 0) ? bq : (sel == 1) ? bk : bv;
        g_bqkv[j] = bb[jj];
    }
}

// ---------------- LayerNorm (tf32-rounded output) ----------------
__global__ __launch_bounds__(256) void ln_kernel(const float* __restrict__ x,
                                                 const float* __restrict__ g,
                                                 const float* __restrict__ bet,
                                                 float* __restrict__ out) {
    int t = blockIdx.x;
    const float* xr = x + (size_t)t * D_;
    float* orow = out + (size_t)t * D_;
    int tid = threadIdx.x;
    float v0 = xr[tid], v1 = xr[tid + 256], v2 = xr[tid + 512];
    float s  = v0 + v1 + v2;
    float ss = v0 * v0 + v1 * v1 + v2 * v2;
    #pragma unroll
    for (int o = 16; o > 0; o >>= 1) {
        s  += __shfl_xor_sync(0xffffffffu, s, o);
        ss += __shfl_xor_sync(0xffffffffu, ss, o);
    }
    __shared__ float sh[16];
    __shared__ float mb[2];
    int w = tid >> 5, lane = tid & 31;
    if (lane == 0) { sh[w] = s; sh[w + 8] = ss; }
    __syncthreads();
    if (tid == 0) {
        float S1 = 0.f, S2 = 0.f;
        #pragma unroll
        for (int i = 0; i < 8; i++) { S1 += sh[i]; S2 += sh[i + 8]; }
        float mean = S1 * (1.0f / D_);
        float var  = S2 * (1.0f / D_) - mean * mean;
        mb[0] = mean;
        mb[1] = rsqrtf(var + 1e-6f);
    }
    __syncthreads();
    float mean = mb[0], rstd = mb[1];
    orow[tid]       = tf32r((v0 - mean) * rstd * g[tid]       + bet[tid]);
    orow[tid + 256] = tf32r((v1 - mean) * rstd * g[tid + 256] + bet[tid + 256]);
    orow[tid + 512] = tf32r((v2 - mean) * rstd * g[tid + 512] + bet[tid + 512]);
}

// ---------------- tf32 SGEMM: 128x128x32, 128 thr (4 warps, 64x64), 3-stage, 2 CTA/SM ----------------
// + software-pipelined fragment loads (R12/R13, unchanged)
#define GBM 128
#define GBN 128
#define GBK 32
#define A_LD 36
#define B_LD 132
#define ASZ (GBM * A_LD)
#define BSZ (GBK * B_LD)
#define GEMM_SMEM_FLOATS (3 * ASZ + 3 * BSZ)
#define GEMM_SMEM_BYTES  (GEMM_SMEM_FLOATS * 4)   // 105,984 B

template <int EPI, bool RND>
__global__ __launch_bounds__(128, 2) void sgemm_tc(const float* __restrict__ A,
                                                   const float* __restrict__ Bw,
                                                   const float* __restrict__ bias,
                                                   const float* __restrict__ res,
                                                   float* __restrict__ C,
                                                   int M, int N, int K) {
    extern __shared__ float dsm[];
    float* As = dsm;
    float* Bs = dsm + 3 * ASZ;

    int tid = threadIdx.x;
    int wid = tid >> 5, lane = tid & 31;
    int warp_m = wid & 1;
    int warp_n = wid >> 1;
    int blockM = blockIdx.y * GBM;
    int blockN = blockIdx.x * GBN;

    int aRow = tid >> 2;
    int aCol = (tid & 3) * 8;
    int bRow = tid >> 5;
    int bCol = (tid & 31) * 4;

    int nk = K / GBK;

    auto issue_tile = [&](int t, int buf) {
        int k0 = t * GBK;
        float* Ad = As + buf * ASZ;
        float* Bd = Bs + buf * BSZ;
        #pragma unroll
        for (int p = 0; p < 4; p++) {
            int r = aRow + p * 32;
            bool ok = (blockM + r) < M;
            const float* gp = A + (size_t)(ok ? (blockM + r) : 0) * K + k0 + aCol;
            cp_async16(Ad + r * A_LD + aCol,     gp,     ok);
            cp_async16(Ad + r * A_LD + aCol + 4, gp + 4, ok);
        }
        #pragma unroll
        for (int p = 0; p < 8; p++) {
            int r = bRow + p * 4;
            const float* gp = Bw + (size_t)(k0 + r) * N + blockN + bCol;
            cp_async16(Bd + r * B_LD + bCol, gp, true);
        }
    };

    wmma::fragment<wmma::accumulator, 16, 16, 8, float> acc[4][4];
    #pragma unroll
    for (int i = 0; i < 4; i++)
        #pragma unroll
        for (int j = 0; j < 4; j++) wmma::fill_fragment(acc[i][j], 0.0f);

    issue_tile(0, 0); cp_commit();
    issue_tile(1, 1); cp_commit();

    int buf = 0;
    for (int t = 0; t < nk; t++) {
        cp_wait<1>();
        __syncthreads();
        if (t + 2 < nk) { issue_tile(t + 2, (buf + 2) % 3); cp_commit(); }

        float* Ab = As + buf * ASZ;
        float* Bb = Bs + buf * BSZ;

        wmma::fragment<wmma::matrix_a, 16, 16, 8, wmma::precision::tf32, wmma::row_major> af[2][4];
        wmma::fragment<wmma::matrix_b, 16, 16, 8, wmma::precision::tf32, wmma::row_major> bf[2][4];
        #pragma unroll
        for (int i = 0; i < 4; i++)
            wmma::load_matrix_sync(af[0][i], Ab + (warp_m * 64 + i * 16) * A_LD, A_LD);
        #pragma unroll
        for (int j = 0; j < 4; j++)
            wmma::load_matrix_sync(bf[0][j], Bb + warp_n * 64 + j * 16, B_LD);

        #pragma unroll
        for (int ks = 0; ks < 4; ks++) {
            int cur = ks & 1, nxt = cur ^ 1;
            if (ks < 3) {
                #pragma unroll
                for (int i = 0; i < 4; i++)
                    wmma::load_matrix_sync(af[nxt][i],
                        Ab + (warp_m * 64 + i * 16) * A_LD + (ks + 1) * 8, A_LD);
                #pragma unroll
                for (int j = 0; j < 4; j++)
                    wmma::load_matrix_sync(bf[nxt][j],
                        Bb + ((ks + 1) * 8) * B_LD + warp_n * 64 + j * 16, B_LD);
            }
            #pragma unroll
            for (int i = 0; i < 4; i++)
                #pragma unroll
                for (int j = 0; j < 4; j++)
                    wmma::mma_sync(acc[i][j], af[cur][i], bf[cur][j], acc[i][j]);
        }
        buf = (buf + 1) % 3;
    }

    __syncthreads();
    float* st = dsm + wid * 320;
    int r  = lane >> 1;
    int c0 = (lane & 1) * 8;
    #pragma unroll
    for (int i = 0; i < 4; i++) {
        #pragma unroll
        for (int j = 0; j < 4; j++) {
            wmma::store_matrix_sync(st, acc[i][j], 20, wmma::mem_row_major);
            __syncwarp();
            int grow = blockM + warp_m * 64 + i * 16 + r;
            int gcol = blockN + warp_n * 64 + j * 16 + c0;
            if (grow < M) {
                #pragma unroll
                for (int cc = 0; cc < 8; cc++) {
                    float v = st[r * 20 + c0 + cc] + bias[gcol + cc];
                    if (EPI == 1) v = gelu_tanh(v);
                    else if (EPI == 2) v += res[(size_t)grow * N + gcol + cc];
                    if (RND) v = tf32r(v);
                    C[(size_t)grow * N + gcol + cc] = v;
                }
            }
            __syncwarp();
        }
    }
}

// ---------------- flash attention: 128-row Q tile, 512 thr / 16 warps, 1 CTA/SM ----------------
// R13 structure + register prefetch of next K/V tile (smem ordering identical to R13)
#define SKT 10
#define TLD 68
#define QROWS 128
#define QS_F  (QROWS * TLD)            // 8704
#define KV_F  (64 * TLD)               // 4352
#define AF_SMEM_FLOATS (QS_F * 3 + KV_F * 2 + QROWS)   // qs, ps, os, ks, vs, crow
#define AF_SMEM_BYTES  (AF_SMEM_FLOATS * 4)            // 139,776 B

__global__ __launch_bounds__(512, 1) void attn_flash(const float* __restrict__ qkv,
                                                     float* __restrict__ attn) {
    extern __shared__ float sm[];
    float* qs   = sm;                         // [128][68]
    float* ps   = sm + QS_F;                  // [128][68]
    float* os   = sm + 2 * QS_F;              // [128][68]
    float* ks   = sm + 3 * QS_F;              // [64][68]
    float* vs   = sm + 3 * QS_F + KV_F;       // [64][68]
    float* crow = sm + 3 * QS_F + 2 * KV_F;   // [128]

    int bh = blockIdx.y;
    int b = bh / H_, h = bh % H_;
    int qt = blockIdx.x;
    int tid = threadIdx.x;
    int wid = tid >> 5, lane = tid & 31;
    int warp_m  = wid & 7;          // 8 x 16 rows
    int warp_nh = wid >> 3;         // 2 x 32 cols

    int lr  = tid >> 2;             // 0..127
    int lc0 = (tid & 3) * 16;
    int kvr = tid >> 3;             // 0..63
    int kvc = (tid & 7) * 8;

    // register prefetch state for one K/V tile
    float4 kr0, kr1, vr0, vr1;
    auto load_regs = [&](int kt) {
        int gk = kt * 64 + kvr;
        bool kok = gk < S_;
        const float* kp = &qkv[((size_t)(b * S_ + (kok ? gk : 0))) * (3 * D_) + D_ + h * DH_];
        const float* vp = &qkv[((size_t)(b * S_ + (kok ? gk : 0))) * (3 * D_) + 2 * D_ + h * DH_];
        kr0 = kok ? *(const float4*)&kp[kvc]     : make_float4(0.f, 0.f, 0.f, 0.f);
        kr1 = kok ? *(const float4*)&kp[kvc + 4] : make_float4(0.f, 0.f, 0.f, 0.f);
        vr0 = kok ? *(const float4*)&vp[kvc]     : make_float4(0.f, 0.f, 0.f, 0.f);
        vr1 = kok ? *(const float4*)&vp[kvc + 4] : make_float4(0.f, 0.f, 0.f, 0.f);
    };

    // load Q tile [128][64], zero O
    {
        int gq = qt * QROWS + lr;
        bool qok = gq < S_;
        const float* qp = &qkv[((size_t)(b * S_ + (qok ? gq : 0))) * (3 * D_) + h * DH_];
        #pragma unroll
        for (int i = 0; i < 4; i++) {
            float4 v = qok ? *(const float4*)&qp[lc0 + i * 4] : make_float4(0.f, 0.f, 0.f, 0.f);
            *(float4*)&qs[lr * TLD + lc0 + i * 4] = v;
        }
        for (int i = tid; i < QS_F; i += 512) os[i] = 0.f;
    }

    load_regs(0);   // prefetch tile 0 while Q/os stores are in flight

    float mrow[8], lrow[8];
    #pragma unroll
    for (int rr = 0; rr < 8; rr++) { mrow[rr] = -1e30f; lrow[rr] = 0.f; }

    for (int kt = 0; kt < SKT; kt++) {
        __syncthreads();   // prev iteration's reads of ks/vs done (and Q visible on iter 0)
        {
            // store the prefetched tile kt to smem (same slot, same barriers as R13)
            *(float4*)&ks[kvr * TLD + kvc]     = kr0;
            *(float4*)&ks[kvr * TLD + kvc + 4] = kr1;
            *(float4*)&vs[kvr * TLD + kvc]     = vr0;
            *(float4*)&vs[kvr * TLD + kvc + 4] = vr1;
        }
        __syncthreads();   // tile kt visible

        // issue next tile's global loads now; consumed at next iteration's store
        if (kt + 1 < SKT) load_regs(kt + 1);

        // S = Q K^T / 8 -> ps [128][64]
        {
            wmma::fragment<wmma::accumulator, 16, 16, 8, float> sacc[2];
            #pragma unroll
            for (int j = 0; j < 2; j++) wmma::fill_fragment(sacc[j], 0.0f);
            #pragma unroll
            for (int kk = 0; kk < 8; kk++) {
                wmma::fragment<wmma::matrix_a, 16, 16, 8, wmma::precision::tf32, wmma::row_major> af;
                wmma::load_matrix_sync(af, qs + (warp_m * 16) * TLD + kk * 8, TLD);
                #pragma unroll
                for (int j = 0; j < 2; j++) {
                    wmma::fragment<wmma::matrix_b, 16, 16, 8, wmma::precision::tf32, wmma::col_major> bf;
                    wmma::load_matrix_sync(bf, ks + (warp_nh * 32 + j * 16) * TLD + kk * 8, TLD);
                    wmma::mma_sync(sacc[j], af, bf, sacc[j]);
                }
            }
            #pragma unroll
            for (int j = 0; j < 2; j++) {
                #pragma unroll
                for (int e = 0; e < sacc[j].num_elements; e++) sacc[j].x[e] *= 0.125f;
                wmma::store_matrix_sync(ps + (warp_m * 16) * TLD + warp_nh * 32 + j * 16,
                                        sacc[j], TLD, wmma::mem_row_major);
            }
        }
        __syncthreads();

        // streaming softmax: warp wid owns rows wid*8 .. wid*8+7
        #pragma unroll
        for (int rr = 0; rr < 8; rr++) {
            int r = wid * 8 + rr;
            float* row = ps + r * TLD;
            int gc0 = kt * 64 + lane;
            int gc1 = gc0 + 32;
            float a0 = (gc0 < S_) ? row[lane]      : -1e30f;
            float a1 = (gc1 < S_) ? row[lane + 32] : -1e30f;
            float tmax = fmaxf(a0, a1);
            #pragma unroll
            for (int o = 16; o > 0; o >>= 1) tmax = fmaxf(tmax, __shfl_xor_sync(0xffffffffu, tmax, o));
            float m_new = fmaxf(mrow[rr], tmax);
            float corr = __expf(mrow[rr] - m_new);
            float p0 = (gc0 < S_) ? __expf(a0 - m_new) : 0.f;
            float p1 = (gc1 < S_) ? __expf(a1 - m_new) : 0.f;
            float tsum = p0 + p1;
            #pragma unroll
            for (int o = 16; o > 0; o >>= 1) tsum += __shfl_xor_sync(0xffffffffu, tsum, o);
            lrow[rr] = lrow[rr] * corr + tsum;
            mrow[rr] = m_new;
            row[lane]      = tf32r(p0);
            row[lane + 32] = tf32r(p1);
            if (lane == 0) crow[r] = corr;
        }
        __syncthreads();

        // rescale O
        {
            float c = crow[lr];
            #pragma unroll
            for (int i = 0; i < 16; i++) os[lr * TLD + lc0 + i] *= c;
        }
        __syncthreads();

        // O += P V
        {
            wmma::fragment<wmma::accumulator, 16, 16, 8, float> oacc[2];
            #pragma unroll
            for (int j = 0; j < 2; j++)
                wmma::load_matrix_sync(oacc[j], os + (warp_m * 16) * TLD + warp_nh * 32 + j * 16,
                                       TLD, wmma::mem_row_major);
            #pragma unroll
            for (int kk = 0; kk < 8; kk++) {
                wmma::fragment<wmma::matrix_a, 16, 16, 8, wmma::precision::tf32, wmma::row_major> af;
                wmma::load_matrix_sync(af, ps + (warp_m * 16) * TLD + kk * 8, TLD);
                #pragma unroll
                for (int j = 0; j < 2; j++) {
                    wmma::fragment<wmma::matrix_b, 16, 16, 8, wmma::precision::tf32, wmma::row_major> bf;
                    wmma::load_matrix_sync(bf, vs + (kk * 8) * TLD + warp_nh * 32 + j * 16, TLD);
                    wmma::mma_sync(oacc[j], af, bf, oacc[j]);
                }
            }
            #pragma unroll
            for (int j = 0; j < 2; j++)
                wmma::store_matrix_sync(os + (warp_m * 16) * TLD + warp_nh * 32 + j * 16,
                                        oacc[j], TLD, wmma::mem_row_major);
        }
    }
    __syncthreads();

    // epilogue: warp wid rows wid*8..+7, divide by l, write (tf32-rounded)
    #pragma unroll
    for (int rr = 0; rr < 8; rr++) {
        int rloc = wid * 8 + rr;
        int gi = qt * QROWS + rloc;
        if (gi >= S_) continue;
        float linv = 1.0f / lrow[rr];
        float* orow = &attn[((size_t)(b * S_ + gi)) * D_ + h * DH_];
        int c = lane * 2;
        orow[c]     = tf32r(os[rloc * TLD + c] * linv);
        orow[c + 1] = tf32r(os[rloc * TLD + c + 1] * linv);
    }
}

// ---------------- launch ----------------
extern "C" void kernel_launch(void* const* d_in, const int* in_sizes, int n_in,
                              void* d_out, int out_size) {
    const float* x     = (const float*)d_in[0];
    const float* ln1_g = (const float*)d_in[1];
    const float* ln1_b = (const float*)d_in[2];
    const float* Wq    = (const float*)d_in[3];
    const float* bq    = (const float*)d_in[4];
    const float* Wk    = (const float*)d_in[5];
    const float* bk    = (const float*)d_in[6];
    const float* Wv    = (const float*)d_in[7];
    const float* bv    = (const float*)d_in[8];
    const float* Wo    = (const float*)d_in[9];
    const float* bo    = (const float*)d_in[10];
    const float* ln2_g = (const float*)d_in[11];
    const float* ln2_b = (const float*)d_in[12];
    const float* W1    = (const float*)d_in[13];
    const float* b1    = (const float*)d_in[14];
    const float* W2    = (const float*)d_in[15];
    const float* b2    = (const float*)d_in[16];
    float* out = (float*)d_out;

    float* h_p;    cudaGetSymbolAddress((void**)&h_p, g_h);
    float* qkv_p;  cudaGetSymbolAddress((void**)&qkv_p, g_qkv);
    float* attn_p; cudaGetSymbolAddress((void**)&attn_p, g_attn);
    float* ff_p;   cudaGetSymbolAddress((void**)&ff_p, g_ff);
    float* wqkv_p; cudaGetSymbolAddress((void**)&wqkv_p, g_wqkv);
    float* bqkv_p; cudaGetSymbolAddress((void**)&bqkv_p, g_bqkv);
    float* wor_p;  cudaGetSymbolAddress((void**)&wor_p, g_wor);
    float* w1r_p;  cudaGetSymbolAddress((void**)&w1r_p, g_w1r);
    float* w2r_p;  cudaGetSymbolAddress((void**)&w2r_p, g_w2r);

    cudaFuncSetAttribute((const void*)sgemm_tc<0, true>,  cudaFuncAttributeMaxDynamicSharedMemorySize, GEMM_SMEM_BYTES);
    cudaFuncSetAttribute((const void*)sgemm_tc<1, true>,  cudaFuncAttributeMaxDynamicSharedMemorySize, GEMM_SMEM_BYTES);
    cudaFuncSetAttribute((const void*)sgemm_tc<2, false>, cudaFuncAttributeMaxDynamicSharedMemorySize, GEMM_SMEM_BYTES);
    cudaFuncSetAttribute((const void*)attn_flash, cudaFuncAttributeMaxDynamicSharedMemorySize, AF_SMEM_BYTES);

    // 0. weight prep
    round_copy3_kernel<<<(N_WF + 255) / 256, 256>>>(Wo, W1, W2);
    {
        size_t total = (size_t)D_ * 3 * D_;
        pack_qkv_kernel<<<(int)((total + 255) / 256), 256>>>(Wq, Wk, Wv, bq, bk, bv);
    }
    // 1. LN1 (rounded output)
    ln_kernel<<<NT_, 256>>>(x, ln1_g, ln1_b, h_p);
    // 2. fused QKV GEMM (rounded output)
    {
        dim3 grid(3 * D_ / GBN, (NT_ + GBM - 1) / GBM);
        sgemm_tc<0, true><<<grid, 128, GEMM_SMEM_BYTES>>>(h_p, wqkv_p, bqkv_p, nullptr, qkv_p, NT_, 3 * D_, D_);
    }
    // 3. flash attention (128-row Q tiles, register prefetch)
    {
        dim3 grid((S_ + QROWS - 1) / QROWS, B_ * H_);
        attn_flash<<<grid, 512, AF_SMEM_BYTES>>>(qkv_p, attn_p);
    }
    // 4. x2 = x + attn @ Wo + bo -> out (full fp32)
    {
        dim3 grid(D_ / GBN, (NT_ + GBM - 1) / GBM);
        sgemm_tc<2, false><<<grid, 128, GEMM_SMEM_BYTES>>>(attn_p, wor_p, bo, x, out, NT_, D_, D_);
    }
    // 5. LN2 (rounded output)
    ln_kernel<<<NT_, 256>>>(out, ln2_g, ln2_b, h_p);
    // 6. ff = gelu(m @ W1 + b1) (rounded output)
    {
        dim3 grid(FF_ / GBN, (NT_ + GBM - 1) / GBM);
        sgemm_tc<1, true><<<grid, 128, GEMM_SMEM_BYTES>>>(h_p, w1r_p, b1, nullptr, ff_p, NT_, FF_, D_);
    }
    // 7. out = x2 + ff @ W2 + b2 (full fp32)
    {
        dim3 grid(D_ / GBN, (NT_ + GBM - 1) / GBM);
        sgemm_tc<2, false><<<grid, 128, GEMM_SMEM_BYTES>>>(ff_p, w2r_p, b2, out, out, NT_, D_, FF_);
    }
}

// round 16
// speedup vs baseline: 1.1352x; 1.0589x over previous
#include <cuda_runtime.h>
#include <cuda_bf16.h>
#include <mma.h>
#include <math.h>

using namespace nvcuda;

#define B_   64
#define S_   577
#define D_   768
#define H_   12
#define DH_  64
#define FF_  3072
#define NT_  (B_ * S_)          // 36928 tokens

// ---------------- scratch ----------------
__device__ float g_h[(size_t)NT_ * D_];
__device__ float g_qkv[(size_t)NT_ * 3 * D_];
__device__ float g_attn[(size_t)NT_ * D_];
__device__ float g_ff[(size_t)NT_ * FF_];
__device__ float g_wqkv[(size_t)D_ * 3 * D_];
__device__ float g_bqkv[3 * D_];
__device__ float g_wor[(size_t)D_ * D_];
__device__ float g_w1r[(size_t)D_ * FF_];
__device__ float g_w2r[(size_t)FF_ * D_];

// ---------------- helpers ----------------
__device__ __forceinline__ float tf32r(float x) { return wmma::__float_to_tf32(x); }

__device__ __forceinline__ float gelu_tanh(float x) {
    const float c = 0.7978845608028654f;
    float x3 = x * x * x;
    return 0.5f * x * (1.0f + tanhf(c * (x + 0.044715f * x3)));
}

__device__ __forceinline__ void cp_async16(float* s, const float* g, bool pred) {
    unsigned saddr = (unsigned)__cvta_generic_to_shared(s);
    int sz = pred ? 16 : 0;
    asm volatile("cp.async.cg.shared.global [%0], [%1], 16, %2;\n"
                 :: "r"(saddr), "l"(g), "r"(sz));
}
__device__ __forceinline__ void cp_commit() { asm volatile("cp.async.commit_group;\n"); }
template <int N>
__device__ __forceinline__ void cp_wait() { asm volatile("cp.async.wait_group %0;\n" :: "n"(N)); }

// ---------------- merged round-copy (RN tf32) for Wo|W1|W2 ----------------
#define N_WO (D_ * D_)
#define N_WF (D_ * FF_)
__global__ void round_copy3_kernel(const float* __restrict__ Wo, const float* __restrict__ W1,
                                   const float* __restrict__ W2) {
    int i = blockIdx.x * blockDim.x + threadIdx.x;
    if (i < N_WO) {
        g_wor[i] = tf32r(Wo[i]);
    }
    if (i < N_WF) {
        g_w1r[i] = tf32r(W1[i]);
        g_w2r[i] = tf32r(W2[i]);
    }
}

// ---------------- pack per-head QKV weights into fused [D, 2304] (rounded) ----------------
__global__ void pack_qkv_kernel(const float* __restrict__ Wq, const float* __restrict__ Wk,
                                const float* __restrict__ Wv, const float* __restrict__ bq,
                                const float* __restrict__ bk, const float* __restrict__ bv) {
    size_t idx = (size_t)blockIdx.x * blockDim.x + threadIdx.x;
    size_t total = (size_t)D_ * 3 * D_;
    if (idx >= total) return;
    int d  = (int)(idx / (3 * D_));
    int j  = (int)(idx % (3 * D_));
    int sel = j / D_;
    int jj  = j % D_;
    int h = jj / DH_;
    int e = jj % DH_;
    const float* W = (sel == 0) ? Wq : (sel == 1) ? Wk : Wv;
    g_wqkv[idx] = tf32r(W[((size_t)h * D_ + d) * DH_ + e]);
    if (d == 0) {
        const float* bb = (sel == 0) ? bq : (sel == 1) ? bk : bv;
        g_bqkv[j] = bb[jj];
    }
}

// ---------------- LayerNorm (tf32-rounded output) ----------------
__global__ __launch_bounds__(256) void ln_kernel(const float* __restrict__ x,
                                                 const float* __restrict__ g,
                                                 const float* __restrict__ bet,
                                                 float* __restrict__ out) {
    int t = blockIdx.x;
    const float* xr = x + (size_t)t * D_;
    float* orow = out + (size_t)t * D_;
    int tid = threadIdx.x;
    float v0 = xr[tid], v1 = xr[tid + 256], v2 = xr[tid + 512];
    float s  = v0 + v1 + v2;
    float ss = v0 * v0 + v1 * v1 + v2 * v2;
    #pragma unroll
    for (int o = 16; o > 0; o >>= 1) {
        s  += __shfl_xor_sync(0xffffffffu, s, o);
        ss += __shfl_xor_sync(0xffffffffu, ss, o);
    }
    __shared__ float sh[16];
    __shared__ float mb[2];
    int w = tid >> 5, lane = tid & 31;
    if (lane == 0) { sh[w] = s; sh[w + 8] = ss; }
    __syncthreads();
    if (tid == 0) {
        float S1 = 0.f, S2 = 0.f;
        #pragma unroll
        for (int i = 0; i < 8; i++) { S1 += sh[i]; S2 += sh[i + 8]; }
        float mean = S1 * (1.0f / D_);
        float var  = S2 * (1.0f / D_) - mean * mean;
        mb[0] = mean;
        mb[1] = rsqrtf(var + 1e-6f);
    }
    __syncthreads();
    float mean = mb[0], rstd = mb[1];
    orow[tid]       = tf32r((v0 - mean) * rstd * g[tid]       + bet[tid]);
    orow[tid + 256] = tf32r((v1 - mean) * rstd * g[tid + 256] + bet[tid + 256]);
    orow[tid + 512] = tf32r((v2 - mean) * rstd * g[tid + 512] + bet[tid + 512]);
}

// ---------------- tf32 SGEMM: 128x128x32, 128 thr (4 warps, 64x64), 3-stage, 2 CTA/SM ----------------
// + software-pipelined fragment loads + float4 epilogue
#define GBM 128
#define GBN 128
#define GBK 32
#define A_LD 36
#define B_LD 132
#define ASZ (GBM * A_LD)
#define BSZ (GBK * B_LD)
#define GEMM_SMEM_FLOATS (3 * ASZ + 3 * BSZ)
#define GEMM_SMEM_BYTES  (GEMM_SMEM_FLOATS * 4)   // 105,984 B

template <int EPI, bool RND>
__global__ __launch_bounds__(128, 2) void sgemm_tc(const float* __restrict__ A,
                                                   const float* __restrict__ Bw,
                                                   const float* __restrict__ bias,
                                                   const float* __restrict__ res,
                                                   float* __restrict__ C,
                                                   int M, int N, int K) {
    extern __shared__ float dsm[];
    float* As = dsm;
    float* Bs = dsm + 3 * ASZ;

    int tid = threadIdx.x;
    int wid = tid >> 5, lane = tid & 31;
    int warp_m = wid & 1;
    int warp_n = wid >> 1;
    int blockM = blockIdx.y * GBM;
    int blockN = blockIdx.x * GBN;

    int aRow = tid >> 2;
    int aCol = (tid & 3) * 8;
    int bRow = tid >> 5;
    int bCol = (tid & 31) * 4;

    int nk = K / GBK;

    auto issue_tile = [&](int t, int buf) {
        int k0 = t * GBK;
        float* Ad = As + buf * ASZ;
        float* Bd = Bs + buf * BSZ;
        #pragma unroll
        for (int p = 0; p < 4; p++) {
            int r = aRow + p * 32;
            bool ok = (blockM + r) < M;
            const float* gp = A + (size_t)(ok ? (blockM + r) : 0) * K + k0 + aCol;
            cp_async16(Ad + r * A_LD + aCol,     gp,     ok);
            cp_async16(Ad + r * A_LD + aCol + 4, gp + 4, ok);
        }
        #pragma unroll
        for (int p = 0; p < 8; p++) {
            int r = bRow + p * 4;
            const float* gp = Bw + (size_t)(k0 + r) * N + blockN + bCol;
            cp_async16(Bd + r * B_LD + bCol, gp, true);
        }
    };

    wmma::fragment<wmma::accumulator, 16, 16, 8, float> acc[4][4];
    #pragma unroll
    for (int i = 0; i < 4; i++)
        #pragma unroll
        for (int j = 0; j < 4; j++) wmma::fill_fragment(acc[i][j], 0.0f);

    issue_tile(0, 0); cp_commit();
    issue_tile(1, 1); cp_commit();

    int buf = 0;
    for (int t = 0; t < nk; t++) {
        cp_wait<1>();
        __syncthreads();
        if (t + 2 < nk) { issue_tile(t + 2, (buf + 2) % 3); cp_commit(); }

        float* Ab = As + buf * ASZ;
        float* Bb = Bs + buf * BSZ;

        wmma::fragment<wmma::matrix_a, 16, 16, 8, wmma::precision::tf32, wmma::row_major> af[2][4];
        wmma::fragment<wmma::matrix_b, 16, 16, 8, wmma::precision::tf32, wmma::row_major> bf[2][4];
        #pragma unroll
        for (int i = 0; i < 4; i++)
            wmma::load_matrix_sync(af[0][i], Ab + (warp_m * 64 + i * 16) * A_LD, A_LD);
        #pragma unroll
        for (int j = 0; j < 4; j++)
            wmma::load_matrix_sync(bf[0][j], Bb + warp_n * 64 + j * 16, B_LD);

        #pragma unroll
        for (int ks = 0; ks < 4; ks++) {
            int cur = ks & 1, nxt = cur ^ 1;
            if (ks < 3) {
                #pragma unroll
                for (int i = 0; i < 4; i++)
                    wmma::load_matrix_sync(af[nxt][i],
                        Ab + (warp_m * 64 + i * 16) * A_LD + (ks + 1) * 8, A_LD);
                #pragma unroll
                for (int j = 0; j < 4; j++)
                    wmma::load_matrix_sync(bf[nxt][j],
                        Bb + ((ks + 1) * 8) * B_LD + warp_n * 64 + j * 16, B_LD);
            }
            #pragma unroll
            for (int i = 0; i < 4; i++)
                #pragma unroll
                for (int j = 0; j < 4; j++)
                    wmma::mma_sync(acc[i][j], af[cur][i], bf[cur][j], acc[i][j]);
        }
        buf = (buf + 1) % 3;
    }

    // float4 epilogue
    __syncthreads();
    float* st = dsm + wid * 320;
    int r  = lane >> 1;
    int c0 = (lane & 1) * 8;
    #pragma unroll
    for (int i = 0; i < 4; i++) {
        #pragma unroll
        for (int j = 0; j < 4; j++) {
            wmma::store_matrix_sync(st, acc[i][j], 20, wmma::mem_row_major);
            __syncwarp();
            int grow = blockM + warp_m * 64 + i * 16 + r;
            int gcol = blockN + warp_n * 64 + j * 16 + c0;
            if (grow < M) {
                float4 v0 = *(const float4*)&st[r * 20 + c0];
                float4 v1 = *(const float4*)&st[r * 20 + c0 + 4];
                float4 b0 = *(const float4*)&bias[gcol];
                float4 b1 = *(const float4*)&bias[gcol + 4];
                v0.x += b0.x; v0.y += b0.y; v0.z += b0.z; v0.w += b0.w;
                v1.x += b1.x; v1.y += b1.y; v1.z += b1.z; v1.w += b1.w;
                if (EPI == 1) {
                    v0.x = gelu_tanh(v0.x); v0.y = gelu_tanh(v0.y);
                    v0.z = gelu_tanh(v0.z); v0.w = gelu_tanh(v0.w);
                    v1.x = gelu_tanh(v1.x); v1.y = gelu_tanh(v1.y);
                    v1.z = gelu_tanh(v1.z); v1.w = gelu_tanh(v1.w);
                } else if (EPI == 2) {
                    const float* rp = &res[(size_t)grow * N + gcol];
                    float4 r0 = *(const float4*)&rp[0];
                    float4 r1 = *(const float4*)&rp[4];
                    v0.x += r0.x; v0.y += r0.y; v0.z += r0.z; v0.w += r0.w;
                    v1.x += r1.x; v1.y += r1.y; v1.z += r1.z; v1.w += r1.w;
                }
                if (RND) {
                    v0.x = tf32r(v0.x); v0.y = tf32r(v0.y); v0.z = tf32r(v0.z); v0.w = tf32r(v0.w);
                    v1.x = tf32r(v1.x); v1.y = tf32r(v1.y); v1.z = tf32r(v1.z); v1.w = tf32r(v1.w);
                }
                float* cp = &C[(size_t)grow * N + gcol];
                *(float4*)&cp[0] = v0;
                *(float4*)&cp[4] = v1;
            }
            __syncwarp();
        }
    }
}

// ---------------- flash attention: 128-row Q tile, 512 thr, register K/V prefetch (R15) ----------------
#define SKT 10
#define TLD 68
#define QROWS 128
#define QS_F  (QROWS * TLD)            // 8704
#define KV_F  (64 * TLD)               // 4352
#define AF_SMEM_FLOATS (QS_F * 3 + KV_F * 2 + QROWS)
#define AF_SMEM_BYTES  (AF_SMEM_FLOATS * 4)            // 139,776 B

__global__ __launch_bounds__(512, 1) void attn_flash(const float* __restrict__ qkv,
                                                     float* __restrict__ attn) {
    extern __shared__ float sm[];
    float* qs   = sm;
    float* ps   = sm + QS_F;
    float* os   = sm + 2 * QS_F;
    float* ks   = sm + 3 * QS_F;
    float* vs   = sm + 3 * QS_F + KV_F;
    float* crow = sm + 3 * QS_F + 2 * KV_F;

    int bh = blockIdx.y;
    int b = bh / H_, h = bh % H_;
    int qt = blockIdx.x;
    int tid = threadIdx.x;
    int wid = tid >> 5, lane = tid & 31;
    int warp_m  = wid & 7;
    int warp_nh = wid >> 3;

    int lr  = tid >> 2;
    int lc0 = (tid & 3) * 16;
    int kvr = tid >> 3;
    int kvc = (tid & 7) * 8;

    float4 kr0, kr1, vr0, vr1;
    auto load_regs = [&](int kt) {
        int gk = kt * 64 + kvr;
        bool kok = gk < S_;
        const float* kp = &qkv[((size_t)(b * S_ + (kok ? gk : 0))) * (3 * D_) + D_ + h * DH_];
        const float* vp = &qkv[((size_t)(b * S_ + (kok ? gk : 0))) * (3 * D_) + 2 * D_ + h * DH_];
        kr0 = kok ? *(const float4*)&kp[kvc]     : make_float4(0.f, 0.f, 0.f, 0.f);
        kr1 = kok ? *(const float4*)&kp[kvc + 4] : make_float4(0.f, 0.f, 0.f, 0.f);
        vr0 = kok ? *(const float4*)&vp[kvc]     : make_float4(0.f, 0.f, 0.f, 0.f);
        vr1 = kok ? *(const float4*)&vp[kvc + 4] : make_float4(0.f, 0.f, 0.f, 0.f);
    };

    {
        int gq = qt * QROWS + lr;
        bool qok = gq < S_;
        const float* qp = &qkv[((size_t)(b * S_ + (qok ? gq : 0))) * (3 * D_) + h * DH_];
        #pragma unroll
        for (int i = 0; i < 4; i++) {
            float4 v = qok ? *(const float4*)&qp[lc0 + i * 4] : make_float4(0.f, 0.f, 0.f, 0.f);
            *(float4*)&qs[lr * TLD + lc0 + i * 4] = v;
        }
        for (int i = tid; i < QS_F; i += 512) os[i] = 0.f;
    }

    load_regs(0);

    float mrow[8], lrow[8];
    #pragma unroll
    for (int rr = 0; rr < 8; rr++) { mrow[rr] = -1e30f; lrow[rr] = 0.f; }

    for (int kt = 0; kt < SKT; kt++) {
        __syncthreads();
        {
            *(float4*)&ks[kvr * TLD + kvc]     = kr0;
            *(float4*)&ks[kvr * TLD + kvc + 4] = kr1;
            *(float4*)&vs[kvr * TLD + kvc]     = vr0;
            *(float4*)&vs[kvr * TLD + kvc + 4] = vr1;
        }
        __syncthreads();

        if (kt + 1 < SKT) load_regs(kt + 1);

        {
            wmma::fragment<wmma::accumulator, 16, 16, 8, float> sacc[2];
            #pragma unroll
            for (int j = 0; j < 2; j++) wmma::fill_fragment(sacc[j], 0.0f);
            #pragma unroll
            for (int kk = 0; kk < 8; kk++) {
                wmma::fragment<wmma::matrix_a, 16, 16, 8, wmma::precision::tf32, wmma::row_major> af;
                wmma::load_matrix_sync(af, qs + (warp_m * 16) * TLD + kk * 8, TLD);
                #pragma unroll
                for (int j = 0; j < 2; j++) {
                    wmma::fragment<wmma::matrix_b, 16, 16, 8, wmma::precision::tf32, wmma::col_major> bf;
                    wmma::load_matrix_sync(bf, ks + (warp_nh * 32 + j * 16) * TLD + kk * 8, TLD);
                    wmma::mma_sync(sacc[j], af, bf, sacc[j]);
                }
            }
            #pragma unroll
            for (int j = 0; j < 2; j++) {
                #pragma unroll
                for (int e = 0; e < sacc[j].num_elements; e++) sacc[j].x[e] *= 0.125f;
                wmma::store_matrix_sync(ps + (warp_m * 16) * TLD + warp_nh * 32 + j * 16,
                                        sacc[j], TLD, wmma::mem_row_major);
            }
        }
        __syncthreads();

        #pragma unroll
        for (int rr = 0; rr < 8; rr++) {
            int r = wid * 8 + rr;
            float* row = ps + r * TLD;
            int gc0 = kt * 64 + lane;
            int gc1 = gc0 + 32;
            float a0 = (gc0 < S_) ? row[lane]      : -1e30f;
            float a1 = (gc1 < S_) ? row[lane + 32] : -1e30f;
            float tmax = fmaxf(a0, a1);
            #pragma unroll
            for (int o = 16; o > 0; o >>= 1) tmax = fmaxf(tmax, __shfl_xor_sync(0xffffffffu, tmax, o));
            float m_new = fmaxf(mrow[rr], tmax);
            float corr = __expf(mrow[rr] - m_new);
            float p0 = (gc0 < S_) ? __expf(a0 - m_new) : 0.f;
            float p1 = (gc1 < S_) ? __expf(a1 - m_new) : 0.f;
            float tsum = p0 + p1;
            #pragma unroll
            for (int o = 16; o > 0; o >>= 1) tsum += __shfl_xor_sync(0xffffffffu, tsum, o);
            lrow[rr] = lrow[rr] * corr + tsum;
            mrow[rr] = m_new;
            row[lane]      = tf32r(p0);
            row[lane + 32] = tf32r(p1);
            if (lane == 0) crow[r] = corr;
        }
        __syncthreads();

        {
            float c = crow[lr];
            #pragma unroll
            for (int i = 0; i < 16; i++) os[lr * TLD + lc0 + i] *= c;
        }
        __syncthreads();

        {
            wmma::fragment<wmma::accumulator, 16, 16, 8, float> oacc[2];
            #pragma unroll
            for (int j = 0; j < 2; j++)
                wmma::load_matrix_sync(oacc[j], os + (warp_m * 16) * TLD + warp_nh * 32 + j * 16,
                                       TLD, wmma::mem_row_major);
            #pragma unroll
            for (int kk = 0; kk < 8; kk++) {
                wmma::fragment<wmma::matrix_a, 16, 16, 8, wmma::precision::tf32, wmma::row_major> af;
                wmma::load_matrix_sync(af, ps + (warp_m * 16) * TLD + kk * 8, TLD);
                #pragma unroll
                for (int j = 0; j < 2; j++) {
                    wmma::fragment<wmma::matrix_b, 16, 16, 8, wmma::precision::tf32, wmma::row_major> bf;
                    wmma::load_matrix_sync(bf, vs + (kk * 8) * TLD + warp_nh * 32 + j * 16, TLD);
                    wmma::mma_sync(oacc[j], af, bf, oacc[j]);
                }
            }
            #pragma unroll
            for (int j = 0; j < 2; j++)
                wmma::store_matrix_sync(os + (warp_m * 16) * TLD + warp_nh * 32 + j * 16,
                                        oacc[j], TLD, wmma::mem_row_major);
        }
    }
    __syncthreads();

    // epilogue (float2 stores)
    #pragma unroll
    for (int rr = 0; rr < 8; rr++) {
        int rloc = wid * 8 + rr;
        int gi = qt * QROWS + rloc;
        if (gi >= S_) continue;
        float linv = 1.0f / lrow[rr];
        float* orow = &attn[((size_t)(b * S_ + gi)) * D_ + h * DH_];
        int c = lane * 2;
        float2 v;
        v.x = tf32r(os[rloc * TLD + c]     * linv);
        v.y = tf32r(os[rloc * TLD + c + 1] * linv);
        *(float2*)&orow[c] = v;
    }
}

// ---------------- launch ----------------
extern "C" void kernel_launch(void* const* d_in, const int* in_sizes, int n_in,
                              void* d_out, int out_size) {
    const float* x     = (const float*)d_in[0];
    const float* ln1_g = (const float*)d_in[1];
    const float* ln1_b = (const float*)d_in[2];
    const float* Wq    = (const float*)d_in[3];
    const float* bq    = (const float*)d_in[4];
    const float* Wk    = (const float*)d_in[5];
    const float* bk    = (const float*)d_in[6];
    const float* Wv    = (const float*)d_in[7];
    const float* bv    = (const float*)d_in[8];
    const float* Wo    = (const float*)d_in[9];
    const float* bo    = (const float*)d_in[10];
    const float* ln2_g = (const float*)d_in[11];
    const float* ln2_b = (const float*)d_in[12];
    const float* W1    = (const float*)d_in[13];
    const float* b1    = (const float*)d_in[14];
    const float* W2    = (const float*)d_in[15];
    const float* b2    = (const float*)d_in[16];
    float* out = (float*)d_out;

    float* h_p;    cudaGetSymbolAddress((void**)&h_p, g_h);
    float* qkv_p;  cudaGetSymbolAddress((void**)&qkv_p, g_qkv);
    float* attn_p; cudaGetSymbolAddress((void**)&attn_p, g_attn);
    float* ff_p;   cudaGetSymbolAddress((void**)&ff_p, g_ff);
    float* wqkv_p; cudaGetSymbolAddress((void**)&wqkv_p, g_wqkv);
    float* bqkv_p; cudaGetSymbolAddress((void**)&bqkv_p, g_bqkv);
    float* wor_p;  cudaGetSymbolAddress((void**)&wor_p, g_wor);
    float* w1r_p;  cudaGetSymbolAddress((void**)&w1r_p, g_w1r);
    float* w2r_p;  cudaGetSymbolAddress((void**)&w2r_p, g_w2r);

    cudaFuncSetAttribute((const void*)sgemm_tc<0, true>,  cudaFuncAttributeMaxDynamicSharedMemorySize, GEMM_SMEM_BYTES);
    cudaFuncSetAttribute((const void*)sgemm_tc<1, true>,  cudaFuncAttributeMaxDynamicSharedMemorySize, GEMM_SMEM_BYTES);
    cudaFuncSetAttribute((const void*)sgemm_tc<2, false>, cudaFuncAttributeMaxDynamicSharedMemorySize, GEMM_SMEM_BYTES);
    cudaFuncSetAttribute((const void*)attn_flash, cudaFuncAttributeMaxDynamicSharedMemorySize, AF_SMEM_BYTES);

    // 0. weight prep
    round_copy3_kernel<<<(N_WF + 255) / 256, 256>>>(Wo, W1, W2);
    {
        size_t total = (size_t)D_ * 3 * D_;
        pack_qkv_kernel<<<(int)((total + 255) / 256), 256>>>(Wq, Wk, Wv, bq, bk, bv);
    }
    // 1. LN1 (rounded output)
    ln_kernel<<<NT_, 256>>>(x, ln1_g, ln1_b, h_p);
    // 2. fused QKV GEMM (rounded output)
    {
        dim3 grid(3 * D_ / GBN, (NT_ + GBM - 1) / GBM);
        sgemm_tc<0, true><<<grid, 128, GEMM_SMEM_BYTES>>>(h_p, wqkv_p, bqkv_p, nullptr, qkv_p, NT_, 3 * D_, D_);
    }
    // 3. flash attention (128-row Q tiles, register prefetch)
    {
        dim3 grid((S_ + QROWS - 1) / QROWS, B_ * H_);
        attn_flash<<<grid, 512, AF_SMEM_BYTES>>>(qkv_p, attn_p);
    }
    // 4. x2 = x + attn @ Wo + bo -> out (full fp32)
    {
        dim3 grid(D_ / GBN, (NT_ + GBM - 1) / GBM);
        sgemm_tc<2, false><<<grid, 128, GEMM_SMEM_BYTES>>>(attn_p, wor_p, bo, x, out, NT_, D_, D_);
    }
    // 5. LN2 (rounded output)
    ln_kernel<<<NT_, 256>>>(out, ln2_g, ln2_b, h_p);
    // 6. ff = gelu(m @ W1 + b1) (rounded output)
    {
        dim3 grid(FF_ / GBN, (NT_ + GBM - 1) / GBM);
        sgemm_tc<1, true><<<grid, 128, GEMM_SMEM_BYTES>>>(h_p, w1r_p, b1, nullptr, ff_p, NT_, FF_, D_);
    }
    // 7. out = x2 + ff @ W2 + b2 (full fp32)
    {
        dim3 grid(D_ / GBN, (NT_ + GBM - 1) / GBM);
        sgemm_tc<2, false><<<grid, 128, GEMM_SMEM_BYTES>>>(ff_p, w2r_p, b2, out, out, NT_, D_, FF_);
    }
}